// round 13
// baseline (speedup 1.0000x reference)
#include <cuda_runtime.h>
#include <cuda_fp16.h>
#include <math.h>
#include <stdint.h>

#define B_   4
#define L_   2048
#define D_   256
#define H_   4
#define NL_  4
#define V_   32000
#define DH_  64
#define FF_  (4*D_)
#define MTOK (B_*L_)

// ---------------- scratch (allocation-free: __device__ globals) ----------------
__device__ float g_x [MTOK*D_];
__device__ float g_xn[MTOK*D_];
__device__ float g_q [MTOK*D_];
__device__ float g_k [MTOK*D_];
__device__ float g_v [MTOK*D_];
__device__ float g_at[MTOK*D_];
__device__ float g_ff[MTOK*FF_];
__device__ __half g_a16[MTOK*D_];                // fp16, pair-permuted
__device__ __half g_w16[(size_t)V_*D_];          // fp16, pair-permuted

// ---------------- embedding ----------------
__global__ void embed_k(const int* __restrict__ ids, const int* __restrict__ tys,
                        const float* __restrict__ tok_emb, const float* __restrict__ type_emb,
                        float* __restrict__ x) {
    int i = blockIdx.x * 256 + threadIdx.x;
    int t = i / D_, d = i - t * D_;
    x[i] = tok_emb[(size_t)ids[t] * D_ + d] + type_emb[tys[t] * D_ + d];
}

// ---------------- RMSNorm ----------------
__global__ void rms_k(const float* __restrict__ x, const float* __restrict__ w,
                      float* __restrict__ y) {
    int row = blockIdx.x;
    int d = threadIdx.x;
    float v = x[(size_t)row * D_ + d];
    float s = v * v;
    __shared__ float sh[8];
    #pragma unroll
    for (int o = 16; o; o >>= 1) s += __shfl_xor_sync(0xFFFFFFFFu, s, o);
    if ((threadIdx.x & 31) == 0) sh[threadIdx.x >> 5] = s;
    __syncthreads();
    if (threadIdx.x < 8) {
        float t = sh[threadIdx.x];
        #pragma unroll
        for (int o = 4; o; o >>= 1) t += __shfl_xor_sync(0xFFu, t, o);
        if (threadIdx.x == 0) sh[0] = t;
    }
    __syncthreads();
    float mean = sh[0] * (1.0f / D_);
    float r = rsqrtf(mean + 1.1920929e-07f);
    y[(size_t)row * D_ + d] = v * r * w[d];
}

// ---------------- RoPE ----------------
__global__ void rope_k(float* __restrict__ q, float* __restrict__ k) {
    int i = blockIdx.x * 256 + threadIdx.x;
    int j  = i & 31;
    int hh = (i >> 5) & (H_ - 1);
    int t  = i >> 7;
    int pos = t & (L_ - 1);
    float freq = expf(-logf(10000.0f) * (float)j * (1.0f / 32.0f));
    float ang = (float)pos * freq;
    float c = cosf(ang), s = sinf(ang);
    size_t base = (size_t)t * D_ + hh * DH_ + j;
    float q0 = q[base], q1 = q[base + 32];
    q[base]      = q0 * c - q1 * s;
    q[base + 32] = q1 * c + q0 * s;
    float k0 = k[base], k1 = k[base + 32];
    k[base]      = k0 * c - k1 * s;
    k[base + 32] = k1 * c + k0 * s;
}

// ---------------- flash-style causal attention (R11 form) ----------------
__global__ void __launch_bounds__(128) attn_k(const float* __restrict__ q,
                                              const float* __restrict__ k,
                                              const float* __restrict__ v,
                                              const int* __restrict__ am,
                                              float* __restrict__ out) {
    int qt = gridDim.x - 1 - blockIdx.x;
    int h = blockIdx.y, b = blockIdx.z;
    int qrow = qt * 128 + threadIdx.x;
    __shared__ float Ks[64][64];
    __shared__ float Vs[64][64];
    __shared__ int   Ms[64];

    float qr[64];
    size_t qbase = ((size_t)(b * L_ + qrow)) * D_ + h * DH_;
    #pragma unroll
    for (int d = 0; d < 64; d++) qr[d] = q[qbase + d] * 0.125f;

    float m = -1e30f, l = 0.0f;
    float acc[64];
    #pragma unroll
    for (int d = 0; d < 64; d++) acc[d] = 0.0f;

    int ntiles = 2 * qt + 2;
    for (int kt = 0; kt < ntiles; kt++) {
        int krow0 = kt * 64;
        {
            int r = threadIdx.x >> 1, half = (threadIdx.x & 1) * 32;
            size_t gb = ((size_t)(b * L_ + krow0 + r)) * D_ + h * DH_ + half;
            float4*       Kd = (float4*)&Ks[r][half];
            const float4* Kg = (const float4*)(k + gb);
            float4*       Vd = (float4*)&Vs[r][half];
            const float4* Vg = (const float4*)(v + gb);
            #pragma unroll
            for (int u = 0; u < 8; u++) { Kd[u] = Kg[u]; Vd[u] = Vg[u]; }
            if (threadIdx.x < 64) Ms[threadIdx.x] = am[b * L_ + krow0 + threadIdx.x];
        }
        __syncthreads();
        int klim = qrow - krow0 + 1;
        if (klim > 64) klim = 64;
        int kk = 0;
        for (; kk + 1 < klim; kk += 2) {
            const float* K0 = Ks[kk];
            const float* K1 = Ks[kk + 1];
            float a0 = 0.f, b0 = 0.f, a1 = 0.f, b1 = 0.f;
            #pragma unroll
            for (int d = 0; d < 64; d += 2) {
                a0 += qr[d]     * K0[d];
                b0 += qr[d + 1] * K0[d + 1];
                a1 += qr[d]     * K1[d];
                b1 += qr[d + 1] * K1[d + 1];
            }
            float s0 = Ms[kk]     ? (a0 + b0) : -1e30f;
            float s1 = Ms[kk + 1] ? (a1 + b1) : -1e30f;
            float sm = fmaxf(s0, s1);
            if (sm > m) {
                float c0 = __expf(m - sm);
                l *= c0;
                #pragma unroll
                for (int d = 0; d < 64; d++) acc[d] *= c0;
                m = sm;
            }
            float p0 = (s0 > -1e29f) ? __expf(s0 - m) : 0.0f;
            float p1 = (s1 > -1e29f) ? __expf(s1 - m) : 0.0f;
            l += p0 + p1;
            const float* V0 = Vs[kk];
            const float* V1 = Vs[kk + 1];
            #pragma unroll
            for (int d = 0; d < 64; d++) acc[d] += p0 * V0[d] + p1 * V1[d];
        }
        if (kk < klim && Ms[kk]) {
            const float* K0 = Ks[kk];
            float a0 = 0.f, b0 = 0.f, c0p = 0.f, d0 = 0.f;
            #pragma unroll
            for (int d = 0; d < 64; d += 4) {
                a0  += qr[d]     * K0[d];
                b0  += qr[d + 1] * K0[d + 1];
                c0p += qr[d + 2] * K0[d + 2];
                d0  += qr[d + 3] * K0[d + 3];
            }
            float s = (a0 + b0) + (c0p + d0);
            if (s > m) {
                float c0 = __expf(m - s);
                l *= c0;
                #pragma unroll
                for (int d = 0; d < 64; d++) acc[d] *= c0;
                m = s;
            }
            float p = __expf(s - m);
            l += p;
            const float* V0 = Vs[kk];
            #pragma unroll
            for (int d = 0; d < 64; d++) acc[d] += p * V0[d];
        }
        __syncthreads();
    }
    float inv = (l > 0.0f) ? (1.0f / l) : 0.0f;
    #pragma unroll
    for (int d = 0; d < 64; d++) out[qbase + d] = acc[d] * inv;
}

// ---------------- fp32 GEMM body (layer path, exact; R8-proven) ----------------
template <int EPI>
__device__ __forceinline__ void gemm_body(const float* __restrict__ A,
                                          const float* __restrict__ W,
                                          const float* __restrict__ R,
                                          float* __restrict__ C,
                                          int N, int K, int bm, int bn) {
    __shared__ __align__(16) float As[2][16][132];
    __shared__ __align__(16) float Ws[2][16][68];
    const int tid = threadIdx.x;
    const int tx = tid & 15, ty = tid >> 4;
    const int arow = tid >> 2;
    const int k4 = (tid & 3) << 2;
    const float* Ap0 = A + (size_t)(bm + arow) * K + k4;
    const float* Ap1 = A + (size_t)(bm + arow + 64) * K + k4;
    const float* Wp  = W + (size_t)(bn + arow) * K + k4;

    float acc[8][4];
    #pragma unroll
    for (int i = 0; i < 8; i++)
        #pragma unroll
        for (int j = 0; j < 4; j++) acc[i][j] = 0.0f;

    float4 pa0 = *(const float4*)Ap0;
    float4 pa1 = *(const float4*)Ap1;
    float4 pw  = *(const float4*)Wp;
    {
        float a0[4] = {pa0.x, pa0.y, pa0.z, pa0.w};
        float a1[4] = {pa1.x, pa1.y, pa1.z, pa1.w};
        float w0[4] = {pw.x,  pw.y,  pw.z,  pw.w};
        #pragma unroll
        for (int j = 0; j < 4; j++) {
            As[0][k4 + j][arow]      = a0[j];
            As[0][k4 + j][arow + 64] = a1[j];
            Ws[0][k4 + j][arow]      = w0[j];
        }
    }
    __syncthreads();

    const int nch = K >> 4;
    for (int ch = 0; ch < nch; ch++) {
        const int s = ch & 1;
        if (ch + 1 < nch) {
            pa0 = *(const float4*)(Ap0 + (ch + 1) * 16);
            pa1 = *(const float4*)(Ap1 + (ch + 1) * 16);
            pw  = *(const float4*)(Wp  + (ch + 1) * 16);
        }
        #pragma unroll
        for (int kk = 0; kk < 16; kk++) {
            float4 av0 = *(const float4*)&As[s][kk][ty * 8];
            float4 av1 = *(const float4*)&As[s][kk][ty * 8 + 4];
            float4 wv  = *(const float4*)&Ws[s][kk][tx * 4];
            float a[8] = {av0.x, av0.y, av0.z, av0.w, av1.x, av1.y, av1.z, av1.w};
            float w[4] = {wv.x, wv.y, wv.z, wv.w};
            #pragma unroll
            for (int i = 0; i < 8; i++)
                #pragma unroll
                for (int j = 0; j < 4; j++) acc[i][j] += a[i] * w[j];
        }
        if (ch + 1 < nch) {
            const int s2 = (ch + 1) & 1;
            float a0[4] = {pa0.x, pa0.y, pa0.z, pa0.w};
            float a1[4] = {pa1.x, pa1.y, pa1.z, pa1.w};
            float w0[4] = {pw.x,  pw.y,  pw.z,  pw.w};
            #pragma unroll
            for (int j = 0; j < 4; j++) {
                As[s2][k4 + j][arow]      = a0[j];
                As[s2][k4 + j][arow + 64] = a1[j];
                Ws[s2][k4 + j][arow]      = w0[j];
            }
        }
        __syncthreads();
    }

    #pragma unroll
    for (int i = 0; i < 8; i++) {
        size_t idx = (size_t)(bm + ty * 8 + i) * N + bn + tx * 4;
        float4 vv = make_float4(acc[i][0], acc[i][1], acc[i][2], acc[i][3]);
        if (EPI == 1) {
            float4 rr = *(const float4*)(R + idx);
            vv.x += rr.x; vv.y += rr.y; vv.z += rr.z; vv.w += rr.w;
        }
        if (EPI == 2) {
            vv.x = vv.x / (1.0f + expf(-vv.x));
            vv.y = vv.y / (1.0f + expf(-vv.y));
            vv.z = vv.z / (1.0f + expf(-vv.z));
            vv.w = vv.w / (1.0f + expf(-vv.w));
        }
        *(float4*)(C + idx) = vv;
    }
}

template <int EPI>
__global__ void __launch_bounds__(256) gemm_f32(const float* __restrict__ A,
                                                const float* __restrict__ W,
                                                const float* __restrict__ R,
                                                float* __restrict__ C,
                                                int M, int N, int K) {
    gemm_body<EPI>(A, W, R, C, N, K, blockIdx.y * 128, blockIdx.x * 64);
}

// fused Q/K/V projection: one launch, blockIdx.x selects matrix + n-tile
__global__ void __launch_bounds__(256) gemm_qkv(const float* __restrict__ A,
                                                const float* __restrict__ Wq,
                                                const float* __restrict__ Wk,
                                                const float* __restrict__ Wv,
                                                float* __restrict__ q,
                                                float* __restrict__ kk,
                                                float* __restrict__ vv,
                                                int K) {
    int sel = blockIdx.x >> 2;
    const float* W = (sel == 0) ? Wq : (sel == 1) ? Wk : Wv;
    float*       C = (sel == 0) ? q  : (sel == 1) ? kk : vv;
    gemm_body<0>(A, W, nullptr, C, D_, K, blockIdx.y * 128, (blockIdx.x & 3) * 64);
}

// ---------------- helpers ----------------
__device__ __forceinline__ uint32_t smem_u32(const void* p) {
    uint32_t a;
    asm("{ .reg .u64 t; cvta.to.shared.u64 t, %1; cvt.u32.u64 %0, t; }" : "=r"(a) : "l"(p));
    return a;
}
#define CP_ASYNC16(dst_u32, src_ptr) \
    asm volatile("cp.async.cg.shared.global [%0], [%1], 16;" :: "r"(dst_u32), "l"(src_ptr))
#define CP_COMMIT() asm volatile("cp.async.commit_group;" ::: "memory")
#define CP_WAIT1()  asm volatile("cp.async.wait_group 1;" ::: "memory")

// fp32 -> fp16, pair-permuted within each 32-k window:
// pair p (0..15) -> pos 4*(p&3) + (p>>2), so pairs {q,4+q,8+q,12+q} are one uint4.
__global__ void cvt_f16_perm(const float* __restrict__ x, __half* __restrict__ o) {
    int i = blockIdx.x * 256 + threadIdx.x;
    int k = i & 31;
    int p = (k >> 1) & 15;
    int pos = 4 * (p & 3) + (p >> 2);
    o[(i & ~31) | (pos * 2 + (k & 1))] = __float2half(x[i]);
}

// ---------------- fp16 mma.sync m16n8k16 GEMM, fp16 ACCUMULATOR (LM head) ----------------
// Testing the half-rate-fp32-acc hypothesis: f16.f16.f16.f16 form, one fp32
// conversion in the epilogue. 128x128 block, 8 warps, warp tile 64x32, BK=32.
__global__ void __launch_bounds__(256, 2) lm_f16(const __half* __restrict__ A,
                                                 const __half* __restrict__ W,
                                                 float* __restrict__ C,
                                                 int M, int N, int K) {
    extern __shared__ __half sh16[];              // 3 stages x (A 4096 | W 4096) halves
    const uint32_t sb = smem_u32(sh16);

    const int bm = blockIdx.y * 128, bn = blockIdx.x * 128;
    const int tid = threadIdx.x;
    const int warp = tid >> 5, lane = tid & 31;
    const int wm = warp >> 2, wn = warp & 3;
    const int gid = lane >> 2, qid = lane & 3;
    const int nchunks = K >> 5;                   // 8

    auto issue = [&](int ch, int s) {
        const uint32_t abase = sb + (uint32_t)(s * 8192) * 2u;
        const uint32_t wbase = abase + 4096u * 2u;
        #pragma unroll
        for (int t = 0; t < 2; t++) {
            int c2 = tid + t * 256;               // 0..511
            int row = c2 >> 2, seg = (c2 & 3) << 3;
            uint32_t dst = (uint32_t)(row * 32 + seg) * 2u;
            CP_ASYNC16(abase + dst, A + (size_t)(bm + row) * K + ch * 32 + seg);
            CP_ASYNC16(wbase + dst, W + (size_t)(bn + row) * K + ch * 32 + seg);
        }
    };

    // fp16 accumulators: 2 b32 regs per 16x8 tile ({c0,c1} row, {c2,c3} row+8)
    unsigned hacc[4][4][2];
    #pragma unroll
    for (int i = 0; i < 4; i++)
        #pragma unroll
        for (int j = 0; j < 4; j++) { hacc[i][j][0] = 0u; hacc[i][j][1] = 0u; }

    issue(0, 0); CP_COMMIT();
    issue(1, 1); CP_COMMIT();

    for (int ch = 0; ch < nchunks; ch++) {
        const int s = ch % 3;
        CP_WAIT1();
        __syncthreads();
        if (ch + 2 < nchunks) {
            issue(ch + 2, (ch + 2) % 3);
            CP_COMMIT();
        }
        const __half* Ab = sh16 + s * 8192;
        const __half* Wb = Ab + 4096;

        uint4 bb[4];
        #pragma unroll
        for (int nt = 0; nt < 4; nt++) {
            int rn = wn * 32 + nt * 8 + gid;
            bb[nt] = *(const uint4*)&Wb[rn * 32 + qid * 8];
        }
        #pragma unroll
        for (int mt = 0; mt < 4; mt++) {
            int r0 = wm * 64 + mt * 16 + gid;
            uint4 lo = *(const uint4*)&Ab[r0 * 32 + qid * 8];
            uint4 hi = *(const uint4*)&Ab[(r0 + 8) * 32 + qid * 8];
            #pragma unroll
            for (int nt = 0; nt < 4; nt++) {
                asm volatile(
                    "mma.sync.aligned.m16n8k16.row.col.f16.f16.f16.f16 "
                    "{%0,%1}, {%2,%3,%4,%5}, {%6,%7}, {%0,%1};\n"
                    : "+r"(hacc[mt][nt][0]), "+r"(hacc[mt][nt][1])
                    : "r"(lo.x), "r"(hi.x), "r"(lo.y), "r"(hi.y),
                      "r"(bb[nt].x), "r"(bb[nt].y));
                asm volatile(
                    "mma.sync.aligned.m16n8k16.row.col.f16.f16.f16.f16 "
                    "{%0,%1}, {%2,%3,%4,%5}, {%6,%7}, {%0,%1};\n"
                    : "+r"(hacc[mt][nt][0]), "+r"(hacc[mt][nt][1])
                    : "r"(lo.z), "r"(hi.z), "r"(lo.w), "r"(hi.w),
                      "r"(bb[nt].z), "r"(bb[nt].w));
            }
        }
    }

    #pragma unroll
    for (int mt = 0; mt < 4; mt++) {
        int row = bm + wm * 64 + mt * 16 + gid;
        #pragma unroll
        for (int nt = 0; nt < 4; nt++) {
            int col = bn + wn * 32 + nt * 8 + qid * 2;
            float2 v0 = __half22float2(*(const __half2*)&hacc[mt][nt][0]);
            float2 v1 = __half22float2(*(const __half2*)&hacc[mt][nt][1]);
            *(float2*)(C + (size_t)row * N + col)       = v0;
            *(float2*)(C + (size_t)(row + 8) * N + col) = v1;
        }
    }
}

// ---------------- classifier heads on cls token (b, 0) ----------------
__global__ void heads_k(const float* __restrict__ xn,
                        const float* __restrict__ rw, const float* __restrict__ rb,
                        const float* __restrict__ mw, const float* __restrict__ mb,
                        float* __restrict__ out) {
    int b = blockIdx.x;
    int t = threadIdx.x;
    float xv = xn[((size_t)b * L_) * D_ + t];
    float pr = xv * rw[t];
    float pm = xv * mw[t];
    __shared__ float sr[8], sm_[8];
    #pragma unroll
    for (int o = 16; o; o >>= 1) {
        pr += __shfl_xor_sync(0xFFFFFFFFu, pr, o);
        pm += __shfl_xor_sync(0xFFFFFFFFu, pm, o);
    }
    if ((t & 31) == 0) { sr[t >> 5] = pr; sm_[t >> 5] = pm; }
    __syncthreads();
    if (t == 0) {
        float a = 0.0f, c = 0.0f;
        #pragma unroll
        for (int i = 0; i < 8; i++) { a += sr[i]; c += sm_[i]; }
        out[b]      = a + rb[0];
        out[B_ + b] = c + mb[0];
    }
}

// ---------------- driver ----------------
extern "C" void kernel_launch(void* const* d_in, const int* in_sizes, int n_in,
                              void* d_out, int out_size) {
    const int*   token_ids    = (const int*)  d_in[0];
    const int*   token_types  = (const int*)  d_in[1];
    const int*   amask        = (const int*)  d_in[2];
    const float* tok_emb      = (const float*)d_in[3];
    const float* type_emb     = (const float*)d_in[4];
    const float* norm1_w      = (const float*)d_in[5];
    const float* wq           = (const float*)d_in[6];
    const float* wk           = (const float*)d_in[7];
    const float* wv           = (const float*)d_in[8];
    const float* wo           = (const float*)d_in[9];
    const float* norm2_w      = (const float*)d_in[10];
    const float* ff_w1        = (const float*)d_in[11];
    const float* ff_w2        = (const float*)d_in[12];
    const float* final_norm_w = (const float*)d_in[13];
    const float* lm_w         = (const float*)d_in[14];
    const float* read_w       = (const float*)d_in[15];
    const float* read_b       = (const float*)d_in[16];
    const float* mort_w       = (const float*)d_in[17];
    const float* mort_b       = (const float*)d_in[18];
    float* out = (float*)d_out;

    float *x, *xn, *q, *k, *v, *at, *ff;
    __half *a16, *w16;
    cudaGetSymbolAddress((void**)&x,   g_x);
    cudaGetSymbolAddress((void**)&xn,  g_xn);
    cudaGetSymbolAddress((void**)&q,   g_q);
    cudaGetSymbolAddress((void**)&k,   g_k);
    cudaGetSymbolAddress((void**)&v,   g_v);
    cudaGetSymbolAddress((void**)&at,  g_at);
    cudaGetSymbolAddress((void**)&ff,  g_ff);
    cudaGetSymbolAddress((void**)&a16, g_a16);
    cudaGetSymbolAddress((void**)&w16, g_w16);

    cudaFuncSetAttribute(lm_f16, cudaFuncAttributeMaxDynamicSharedMemorySize, 49152);

    embed_k<<<MTOK * D_ / 256, 256>>>(token_ids, token_types, tok_emb, type_emb, x);

    dim3 gqkv(D_ / 64, MTOK / 128);
    dim3 gqkv3(3 * D_ / 64, MTOK / 128);
    dim3 gff1(FF_ / 64, MTOK / 128);
    for (int li = 0; li < NL_; li++) {
        rms_k<<<MTOK, 256>>>(x, norm1_w + li * D_, xn);
        gemm_qkv<<<gqkv3, 256>>>(xn, wq + (size_t)li * D_ * D_, wk + (size_t)li * D_ * D_,
                                 wv + (size_t)li * D_ * D_, q, k, v, D_);
        rope_k<<<MTOK * H_ * 32 / 256, 256>>>(q, k);
        attn_k<<<dim3(L_ / 128, H_, B_), 128>>>(q, k, v, amask, at);
        gemm_f32<1><<<gqkv, 256>>>(at, wo + (size_t)li * D_ * D_, x, x, MTOK, D_, D_);
        rms_k<<<MTOK, 256>>>(x, norm2_w + li * D_, xn);
        gemm_f32<2><<<gff1, 256>>>(xn, ff_w1 + (size_t)li * FF_ * D_, nullptr, ff, MTOK, FF_, D_);
        gemm_f32<1><<<gqkv, 256>>>(ff, ff_w2 + (size_t)li * D_ * FF_, x, x, MTOK, D_, FF_);
    }
    rms_k<<<MTOK, 256>>>(x, final_norm_w, xn);
    cvt_f16_perm<<<MTOK * D_ / 256, 256>>>(xn, a16);
    cvt_f16_perm<<<V_ * D_ / 256, 256>>>(lm_w, w16);
    lm_f16<<<dim3(V_ / 128, MTOK / 128), 256, 49152>>>(a16, w16, out, MTOK, V_, D_);
    heads_k<<<B_, 256>>>(xn, read_w, read_b, mort_w, mort_b, out + (size_t)MTOK * V_);
}

// round 14
// speedup vs baseline: 2.0917x; 2.0917x over previous
#include <cuda_runtime.h>
#include <cuda_fp16.h>
#include <math.h>
#include <stdint.h>

#define B_   4
#define L_   2048
#define D_   256
#define H_   4
#define NL_  4
#define V_   32000
#define DH_  64
#define FF_  (4*D_)
#define MTOK (B_*L_)

// ---------------- scratch (allocation-free: __device__ globals) ----------------
__device__ float g_x [MTOK*D_];
__device__ float g_xn[MTOK*D_];
__device__ float g_q [MTOK*D_];
__device__ float g_k [MTOK*D_];
__device__ float g_v [MTOK*D_];
__device__ float g_at[MTOK*D_];
__device__ float g_ff[MTOK*FF_];
__device__ __half g_a16[MTOK*D_];                // fp16, pair-permuted
__device__ __half g_w16[(size_t)V_*D_];          // fp16, pair-permuted

// ---------------- embedding ----------------
__global__ void embed_k(const int* __restrict__ ids, const int* __restrict__ tys,
                        const float* __restrict__ tok_emb, const float* __restrict__ type_emb,
                        float* __restrict__ x) {
    int i = blockIdx.x * 256 + threadIdx.x;
    int t = i / D_, d = i - t * D_;
    x[i] = tok_emb[(size_t)ids[t] * D_ + d] + type_emb[tys[t] * D_ + d];
}

// ---------------- RMSNorm ----------------
__global__ void rms_k(const float* __restrict__ x, const float* __restrict__ w,
                      float* __restrict__ y) {
    int row = blockIdx.x;
    int d = threadIdx.x;
    float v = x[(size_t)row * D_ + d];
    float s = v * v;
    __shared__ float sh[8];
    #pragma unroll
    for (int o = 16; o; o >>= 1) s += __shfl_xor_sync(0xFFFFFFFFu, s, o);
    if ((threadIdx.x & 31) == 0) sh[threadIdx.x >> 5] = s;
    __syncthreads();
    if (threadIdx.x < 8) {
        float t = sh[threadIdx.x];
        #pragma unroll
        for (int o = 4; o; o >>= 1) t += __shfl_xor_sync(0xFFu, t, o);
        if (threadIdx.x == 0) sh[0] = t;
    }
    __syncthreads();
    float mean = sh[0] * (1.0f / D_);
    float r = rsqrtf(mean + 1.1920929e-07f);
    y[(size_t)row * D_ + d] = v * r * w[d];
}

// ---------------- RoPE ----------------
__global__ void rope_k(float* __restrict__ q, float* __restrict__ k) {
    int i = blockIdx.x * 256 + threadIdx.x;
    int j  = i & 31;
    int hh = (i >> 5) & (H_ - 1);
    int t  = i >> 7;
    int pos = t & (L_ - 1);
    float freq = expf(-logf(10000.0f) * (float)j * (1.0f / 32.0f));
    float ang = (float)pos * freq;
    float c = cosf(ang), s = sinf(ang);
    size_t base = (size_t)t * D_ + hh * DH_ + j;
    float q0 = q[base], q1 = q[base + 32];
    q[base]      = q0 * c - q1 * s;
    q[base + 32] = q1 * c + q0 * s;
    float k0 = k[base], k1 = k[base + 32];
    k[base]      = k0 * c - k1 * s;
    k[base + 32] = k1 * c + k0 * s;
}

// ---------------- tensor-core flash attention ----------------
// 128 threads = 4 warps; warp handles 16 queries (m16). fp16 m16n8k16 for
// S=QK^T and P*V, fp32 accumulators, softmax in fragment domain.
// Each CTA processes qt pair {31-bx, bx} -> exactly 33 key tiles (balanced).
#define MMA16(cc, a0, a1, a2, a3, bb0, bb1) \
    asm volatile("mma.sync.aligned.m16n8k16.row.col.f32.f16.f16.f32 " \
                 "{%0,%1,%2,%3}, {%4,%5,%6,%7}, {%8,%9}, {%0,%1,%2,%3};\n" \
                 : "+f"((cc)[0]), "+f"((cc)[1]), "+f"((cc)[2]), "+f"((cc)[3]) \
                 : "r"(a0), "r"(a1), "r"(a2), "r"(a3), "r"(bb0), "r"(bb1))

__device__ __forceinline__ unsigned f2h2(float a, float b) {
    __half2 h = __floats2half2_rn(a, b);
    return *(unsigned*)&h;
}

__global__ void __launch_bounds__(128) attn_tc(const float* __restrict__ q,
                                               const float* __restrict__ k,
                                               const float* __restrict__ v,
                                               const int* __restrict__ am,
                                               float* __restrict__ out) {
    const int h = blockIdx.y, b = blockIdx.z;
    const int tid = threadIdx.x, warp = tid >> 5, lane = tid & 31;
    const int g = lane >> 2, t4 = lane & 3;

    __shared__ __half Ks[64][72];     // [key][dim]
    __shared__ __half Vt[64][72];     // [dim][key]
    __shared__ int Ms[64];

    for (int hf = 0; hf < 2; hf++) {
        const int qt = (hf == 0) ? (int)(gridDim.x * 2 - 1 - blockIdx.x) : (int)blockIdx.x;
        const int rl0 = warp * 16 + g;      // local row of c0,c1
        const int rl1 = rl0 + 8;            // local row of c2,c3

        // Q fragments (scale folded)
        unsigned qa[4][4];
        {
            size_t qr0 = ((size_t)(b * L_) + qt * 64 + rl0) * D_ + h * DH_;
            size_t qr1 = qr0 + 8 * (size_t)D_;
            #pragma unroll
            for (int ks = 0; ks < 4; ks++) {
                int d0 = ks * 16 + t4 * 2;
                float2 x0 = *(const float2*)(q + qr0 + d0);
                float2 x1 = *(const float2*)(q + qr1 + d0);
                float2 x2 = *(const float2*)(q + qr0 + d0 + 8);
                float2 x3 = *(const float2*)(q + qr1 + d0 + 8);
                qa[ks][0] = f2h2(x0.x * 0.125f, x0.y * 0.125f);
                qa[ks][1] = f2h2(x1.x * 0.125f, x1.y * 0.125f);
                qa[ks][2] = f2h2(x2.x * 0.125f, x2.y * 0.125f);
                qa[ks][3] = f2h2(x3.x * 0.125f, x3.y * 0.125f);
            }
        }

        float m0 = -1e30f, m1 = -1e30f, l0 = 0.0f, l1 = 0.0f;
        float oa[8][4];
        #pragma unroll
        for (int dt = 0; dt < 8; dt++)
            #pragma unroll
            for (int f = 0; f < 4; f++) oa[dt][f] = 0.0f;

        for (int kt = 0; kt <= qt; kt++) {
            {   // K tile: thread -> (key, half of dims)
                int key = tid >> 1, dh = (tid & 1) * 32;
                const float* kg = k + ((size_t)(b * L_) + kt * 64 + key) * D_ + h * DH_ + dh;
                #pragma unroll
                for (int j = 0; j < 32; j += 4) {
                    float4 xv = *(const float4*)(kg + j);
                    *(__half2*)&Ks[key][dh + j]     = __floats2half2_rn(xv.x, xv.y);
                    *(__half2*)&Ks[key][dh + j + 2] = __floats2half2_rn(xv.z, xv.w);
                }
                // V transposed: thread -> (keypair, 16 dims)
                int kp = tid & 31, dq = tid >> 5;
                const float* v0 = v + ((size_t)(b * L_) + kt * 64 + 2 * kp) * D_ + h * DH_ + dq * 16;
                const float* v1 = v0 + D_;
                #pragma unroll
                for (int j = 0; j < 16; j += 4) {
                    float4 a = *(const float4*)(v0 + j);
                    float4 c = *(const float4*)(v1 + j);
                    *(__half2*)&Vt[dq * 16 + j][2 * kp]     = __floats2half2_rn(a.x, c.x);
                    *(__half2*)&Vt[dq * 16 + j + 1][2 * kp] = __floats2half2_rn(a.y, c.y);
                    *(__half2*)&Vt[dq * 16 + j + 2][2 * kp] = __floats2half2_rn(a.z, c.z);
                    *(__half2*)&Vt[dq * 16 + j + 3][2 * kp] = __floats2half2_rn(a.w, c.w);
                }
                if (tid < 64) Ms[tid] = am[b * L_ + kt * 64 + tid];
            }
            __syncthreads();

            // S = Q K^T
            float sac[8][4];
            #pragma unroll
            for (int nt = 0; nt < 8; nt++)
                #pragma unroll
                for (int f = 0; f < 4; f++) sac[nt][f] = 0.0f;
            #pragma unroll
            for (int nt = 0; nt < 8; nt++) {
                #pragma unroll
                for (int ks = 0; ks < 4; ks++) {
                    unsigned bb0 = *(const unsigned*)&Ks[nt * 8 + g][ks * 16 + t4 * 2];
                    unsigned bb1 = *(const unsigned*)&Ks[nt * 8 + g][ks * 16 + t4 * 2 + 8];
                    MMA16(sac[nt], qa[ks][0], qa[ks][1], qa[ks][2], qa[ks][3], bb0, bb1);
                }
            }

            // mask (pad + causal on last tile)
            const bool last = (kt == qt);
            float mx0 = -1e30f, mx1 = -1e30f;
            #pragma unroll
            for (int nt = 0; nt < 8; nt++) {
                int c0 = nt * 8 + t4 * 2, c1 = c0 + 1;
                bool p0 = Ms[c0] != 0, p1 = Ms[c1] != 0;
                sac[nt][0] = (p0 && (!last || c0 <= rl0)) ? sac[nt][0] : -1e30f;
                sac[nt][1] = (p1 && (!last || c1 <= rl0)) ? sac[nt][1] : -1e30f;
                sac[nt][2] = (p0 && (!last || c0 <= rl1)) ? sac[nt][2] : -1e30f;
                sac[nt][3] = (p1 && (!last || c1 <= rl1)) ? sac[nt][3] : -1e30f;
                mx0 = fmaxf(mx0, fmaxf(sac[nt][0], sac[nt][1]));
                mx1 = fmaxf(mx1, fmaxf(sac[nt][2], sac[nt][3]));
            }
            mx0 = fmaxf(mx0, __shfl_xor_sync(0xFFFFFFFFu, mx0, 1));
            mx0 = fmaxf(mx0, __shfl_xor_sync(0xFFFFFFFFu, mx0, 2));
            mx1 = fmaxf(mx1, __shfl_xor_sync(0xFFFFFFFFu, mx1, 1));
            mx1 = fmaxf(mx1, __shfl_xor_sync(0xFFFFFFFFu, mx1, 2));
            float mn0 = fmaxf(m0, mx0), mn1 = fmaxf(m1, mx1);
            float sc0 = __expf(m0 - mn0), sc1 = __expf(m1 - mn1);
            m0 = mn0; m1 = mn1;

            float rs0 = 0.0f, rs1 = 0.0f;
            #pragma unroll
            for (int nt = 0; nt < 8; nt++) {
                sac[nt][0] = (sac[nt][0] > -1e29f) ? __expf(sac[nt][0] - m0) : 0.0f;
                sac[nt][1] = (sac[nt][1] > -1e29f) ? __expf(sac[nt][1] - m0) : 0.0f;
                sac[nt][2] = (sac[nt][2] > -1e29f) ? __expf(sac[nt][2] - m1) : 0.0f;
                sac[nt][3] = (sac[nt][3] > -1e29f) ? __expf(sac[nt][3] - m1) : 0.0f;
                rs0 += sac[nt][0] + sac[nt][1];
                rs1 += sac[nt][2] + sac[nt][3];
            }
            rs0 += __shfl_xor_sync(0xFFFFFFFFu, rs0, 1);
            rs0 += __shfl_xor_sync(0xFFFFFFFFu, rs0, 2);
            rs1 += __shfl_xor_sync(0xFFFFFFFFu, rs1, 1);
            rs1 += __shfl_xor_sync(0xFFFFFFFFu, rs1, 2);
            l0 = l0 * sc0 + rs0;
            l1 = l1 * sc1 + rs1;
            #pragma unroll
            for (int dt = 0; dt < 8; dt++) {
                oa[dt][0] *= sc0; oa[dt][1] *= sc0;
                oa[dt][2] *= sc1; oa[dt][3] *= sc1;
            }

            // P fragments (fp16): C-layout of S == A-layout of PV mma
            unsigned pa[4][4];
            #pragma unroll
            for (int kp = 0; kp < 4; kp++) {
                pa[kp][0] = f2h2(sac[2 * kp][0],     sac[2 * kp][1]);
                pa[kp][1] = f2h2(sac[2 * kp][2],     sac[2 * kp][3]);
                pa[kp][2] = f2h2(sac[2 * kp + 1][0], sac[2 * kp + 1][1]);
                pa[kp][3] = f2h2(sac[2 * kp + 1][2], sac[2 * kp + 1][3]);
            }
            #pragma unroll
            for (int dt = 0; dt < 8; dt++) {
                #pragma unroll
                for (int kp = 0; kp < 4; kp++) {
                    unsigned bb0 = *(const unsigned*)&Vt[dt * 8 + g][kp * 16 + t4 * 2];
                    unsigned bb1 = *(const unsigned*)&Vt[dt * 8 + g][kp * 16 + t4 * 2 + 8];
                    MMA16(oa[dt], pa[kp][0], pa[kp][1], pa[kp][2], pa[kp][3], bb0, bb1);
                }
            }
            __syncthreads();
        }

        float inv0 = (l0 > 0.0f) ? (1.0f / l0) : 0.0f;
        float inv1 = (l1 > 0.0f) ? (1.0f / l1) : 0.0f;
        size_t ob = ((size_t)(b * L_) + qt * 64 + rl0) * D_ + h * DH_;
        #pragma unroll
        for (int dt = 0; dt < 8; dt++) {
            *(float2*)(out + ob + dt * 8 + t4 * 2) =
                make_float2(oa[dt][0] * inv0, oa[dt][1] * inv0);
            *(float2*)(out + ob + 8 * (size_t)D_ + dt * 8 + t4 * 2) =
                make_float2(oa[dt][2] * inv1, oa[dt][3] * inv1);
        }
    }
}

// ---------------- fp32 GEMM body (layer path, exact; R8-proven) ----------------
template <int EPI>
__device__ __forceinline__ void gemm_body(const float* __restrict__ A,
                                          const float* __restrict__ W,
                                          const float* __restrict__ R,
                                          float* __restrict__ C,
                                          int N, int K, int bm, int bn) {
    __shared__ __align__(16) float As[2][16][132];
    __shared__ __align__(16) float Ws[2][16][68];
    const int tid = threadIdx.x;
    const int tx = tid & 15, ty = tid >> 4;
    const int arow = tid >> 2;
    const int k4 = (tid & 3) << 2;
    const float* Ap0 = A + (size_t)(bm + arow) * K + k4;
    const float* Ap1 = A + (size_t)(bm + arow + 64) * K + k4;
    const float* Wp  = W + (size_t)(bn + arow) * K + k4;

    float acc[8][4];
    #pragma unroll
    for (int i = 0; i < 8; i++)
        #pragma unroll
        for (int j = 0; j < 4; j++) acc[i][j] = 0.0f;

    float4 pa0 = *(const float4*)Ap0;
    float4 pa1 = *(const float4*)Ap1;
    float4 pw  = *(const float4*)Wp;
    {
        float a0[4] = {pa0.x, pa0.y, pa0.z, pa0.w};
        float a1[4] = {pa1.x, pa1.y, pa1.z, pa1.w};
        float w0[4] = {pw.x,  pw.y,  pw.z,  pw.w};
        #pragma unroll
        for (int j = 0; j < 4; j++) {
            As[0][k4 + j][arow]      = a0[j];
            As[0][k4 + j][arow + 64] = a1[j];
            Ws[0][k4 + j][arow]      = w0[j];
        }
    }
    __syncthreads();

    const int nch = K >> 4;
    for (int ch = 0; ch < nch; ch++) {
        const int s = ch & 1;
        if (ch + 1 < nch) {
            pa0 = *(const float4*)(Ap0 + (ch + 1) * 16);
            pa1 = *(const float4*)(Ap1 + (ch + 1) * 16);
            pw  = *(const float4*)(Wp  + (ch + 1) * 16);
        }
        #pragma unroll
        for (int kk = 0; kk < 16; kk++) {
            float4 av0 = *(const float4*)&As[s][kk][ty * 8];
            float4 av1 = *(const float4*)&As[s][kk][ty * 8 + 4];
            float4 wv  = *(const float4*)&Ws[s][kk][tx * 4];
            float a[8] = {av0.x, av0.y, av0.z, av0.w, av1.x, av1.y, av1.z, av1.w};
            float w[4] = {wv.x, wv.y, wv.z, wv.w};
            #pragma unroll
            for (int i = 0; i < 8; i++)
                #pragma unroll
                for (int j = 0; j < 4; j++) acc[i][j] += a[i] * w[j];
        }
        if (ch + 1 < nch) {
            const int s2 = (ch + 1) & 1;
            float a0[4] = {pa0.x, pa0.y, pa0.z, pa0.w};
            float a1[4] = {pa1.x, pa1.y, pa1.z, pa1.w};
            float w0[4] = {pw.x,  pw.y,  pw.z,  pw.w};
            #pragma unroll
            for (int j = 0; j < 4; j++) {
                As[s2][k4 + j][arow]      = a0[j];
                As[s2][k4 + j][arow + 64] = a1[j];
                Ws[s2][k4 + j][arow]      = w0[j];
            }
        }
        __syncthreads();
    }

    #pragma unroll
    for (int i = 0; i < 8; i++) {
        size_t idx = (size_t)(bm + ty * 8 + i) * N + bn + tx * 4;
        float4 vv = make_float4(acc[i][0], acc[i][1], acc[i][2], acc[i][3]);
        if (EPI == 1) {
            float4 rr = *(const float4*)(R + idx);
            vv.x += rr.x; vv.y += rr.y; vv.z += rr.z; vv.w += rr.w;
        }
        if (EPI == 2) {
            vv.x = vv.x / (1.0f + expf(-vv.x));
            vv.y = vv.y / (1.0f + expf(-vv.y));
            vv.z = vv.z / (1.0f + expf(-vv.z));
            vv.w = vv.w / (1.0f + expf(-vv.w));
        }
        *(float4*)(C + idx) = vv;
    }
}

template <int EPI>
__global__ void __launch_bounds__(256) gemm_f32(const float* __restrict__ A,
                                                const float* __restrict__ W,
                                                const float* __restrict__ R,
                                                float* __restrict__ C,
                                                int M, int N, int K) {
    gemm_body<EPI>(A, W, R, C, N, K, blockIdx.y * 128, blockIdx.x * 64);
}

// fused Q/K/V projection: one launch, blockIdx.x selects matrix + n-tile
__global__ void __launch_bounds__(256) gemm_qkv(const float* __restrict__ A,
                                                const float* __restrict__ Wq,
                                                const float* __restrict__ Wk,
                                                const float* __restrict__ Wv,
                                                float* __restrict__ q,
                                                float* __restrict__ kk,
                                                float* __restrict__ vv,
                                                int K) {
    int sel = blockIdx.x >> 2;
    const float* W = (sel == 0) ? Wq : (sel == 1) ? Wk : Wv;
    float*       C = (sel == 0) ? q  : (sel == 1) ? kk : vv;
    gemm_body<0>(A, W, nullptr, C, D_, K, blockIdx.y * 128, (blockIdx.x & 3) * 64);
}

// ---------------- helpers ----------------
__device__ __forceinline__ uint32_t smem_u32(const void* p) {
    uint32_t a;
    asm("{ .reg .u64 t; cvta.to.shared.u64 t, %1; cvt.u32.u64 %0, t; }" : "=r"(a) : "l"(p));
    return a;
}
#define CP_ASYNC16(dst_u32, src_ptr) \
    asm volatile("cp.async.cg.shared.global [%0], [%1], 16;" :: "r"(dst_u32), "l"(src_ptr))
#define CP_COMMIT() asm volatile("cp.async.commit_group;" ::: "memory")
#define CP_WAIT1()  asm volatile("cp.async.wait_group 1;" ::: "memory")

// fp32 -> fp16, pair-permuted within each 32-k window:
// pair p (0..15) -> pos 4*(p&3) + (p>>2), so pairs {q,4+q,8+q,12+q} are one uint4.
__global__ void cvt_f16_perm(const float* __restrict__ x, __half* __restrict__ o) {
    int i = blockIdx.x * 256 + threadIdx.x;
    int k = i & 31;
    int p = (k >> 1) & 15;
    int pos = 4 * (p & 3) + (p >> 2);
    o[(i & ~31) | (pos * 2 + (k & 1))] = __float2half(x[i]);
}

// ---------------- fp16 mma.sync m16n8k16 GEMM, fp32 acc (LM head; R12-proven) ----------------
__global__ void __launch_bounds__(256, 2) lm_f16(const __half* __restrict__ A,
                                                 const __half* __restrict__ W,
                                                 float* __restrict__ C,
                                                 int M, int N, int K) {
    extern __shared__ __half sh16[];              // 3 stages x (A 4096 | W 4096) halves
    const uint32_t sb = smem_u32(sh16);

    const int bm = blockIdx.y * 128, bn = blockIdx.x * 128;
    const int tid = threadIdx.x;
    const int warp = tid >> 5, lane = tid & 31;
    const int wm = warp >> 2, wn = warp & 3;
    const int gid = lane >> 2, qid = lane & 3;
    const int nchunks = K >> 5;                   // 8

    auto issue = [&](int ch, int s) {
        const uint32_t abase = sb + (uint32_t)(s * 8192) * 2u;
        const uint32_t wbase = abase + 4096u * 2u;
        #pragma unroll
        for (int t = 0; t < 2; t++) {
            int c2 = tid + t * 256;
            int row = c2 >> 2, seg = (c2 & 3) << 3;
            uint32_t dst = (uint32_t)(row * 32 + seg) * 2u;
            CP_ASYNC16(abase + dst, A + (size_t)(bm + row) * K + ch * 32 + seg);
            CP_ASYNC16(wbase + dst, W + (size_t)(bn + row) * K + ch * 32 + seg);
        }
    };

    float cacc[4][4][4];
    #pragma unroll
    for (int i = 0; i < 4; i++)
        #pragma unroll
        for (int j = 0; j < 4; j++)
            #pragma unroll
            for (int f = 0; f < 4; f++) cacc[i][j][f] = 0.0f;

    issue(0, 0); CP_COMMIT();
    issue(1, 1); CP_COMMIT();

    for (int ch = 0; ch < nchunks; ch++) {
        const int s = ch % 3;
        CP_WAIT1();
        __syncthreads();
        if (ch + 2 < nchunks) {
            issue(ch + 2, (ch + 2) % 3);
            CP_COMMIT();
        }
        const __half* Ab = sh16 + s * 8192;
        const __half* Wb = Ab + 4096;

        uint4 bb[4];
        #pragma unroll
        for (int nt = 0; nt < 4; nt++) {
            int rn = wn * 32 + nt * 8 + gid;
            bb[nt] = *(const uint4*)&Wb[rn * 32 + qid * 8];
        }
        #pragma unroll
        for (int mt = 0; mt < 4; mt++) {
            int r0 = wm * 64 + mt * 16 + gid;
            uint4 lo = *(const uint4*)&Ab[r0 * 32 + qid * 8];
            uint4 hi = *(const uint4*)&Ab[(r0 + 8) * 32 + qid * 8];
            #pragma unroll
            for (int nt = 0; nt < 4; nt++) {
                asm volatile(
                    "mma.sync.aligned.m16n8k16.row.col.f32.f16.f16.f32 "
                    "{%0,%1,%2,%3}, {%4,%5,%6,%7}, {%8,%9}, {%0,%1,%2,%3};\n"
                    : "+f"(cacc[mt][nt][0]), "+f"(cacc[mt][nt][1]),
                      "+f"(cacc[mt][nt][2]), "+f"(cacc[mt][nt][3])
                    : "r"(lo.x), "r"(hi.x), "r"(lo.y), "r"(hi.y),
                      "r"(bb[nt].x), "r"(bb[nt].y));
                asm volatile(
                    "mma.sync.aligned.m16n8k16.row.col.f32.f16.f16.f32 "
                    "{%0,%1,%2,%3}, {%4,%5,%6,%7}, {%8,%9}, {%0,%1,%2,%3};\n"
                    : "+f"(cacc[mt][nt][0]), "+f"(cacc[mt][nt][1]),
                      "+f"(cacc[mt][nt][2]), "+f"(cacc[mt][nt][3])
                    : "r"(lo.z), "r"(hi.z), "r"(lo.w), "r"(hi.w),
                      "r"(bb[nt].z), "r"(bb[nt].w));
            }
        }
    }

    #pragma unroll
    for (int mt = 0; mt < 4; mt++) {
        int row = bm + wm * 64 + mt * 16 + gid;
        #pragma unroll
        for (int nt = 0; nt < 4; nt++) {
            int col = bn + wn * 32 + nt * 8 + qid * 2;
            *(float2*)(C + (size_t)row * N + col) =
                make_float2(cacc[mt][nt][0], cacc[mt][nt][1]);
            *(float2*)(C + (size_t)(row + 8) * N + col) =
                make_float2(cacc[mt][nt][2], cacc[mt][nt][3]);
        }
    }
}

// ---------------- classifier heads on cls token (b, 0) ----------------
__global__ void heads_k(const float* __restrict__ xn,
                        const float* __restrict__ rw, const float* __restrict__ rb,
                        const float* __restrict__ mw, const float* __restrict__ mb,
                        float* __restrict__ out) {
    int b = blockIdx.x;
    int t = threadIdx.x;
    float xv = xn[((size_t)b * L_) * D_ + t];
    float pr = xv * rw[t];
    float pm = xv * mw[t];
    __shared__ float sr[8], sm_[8];
    #pragma unroll
    for (int o = 16; o; o >>= 1) {
        pr += __shfl_xor_sync(0xFFFFFFFFu, pr, o);
        pm += __shfl_xor_sync(0xFFFFFFFFu, pm, o);
    }
    if ((t & 31) == 0) { sr[t >> 5] = pr; sm_[t >> 5] = pm; }
    __syncthreads();
    if (t == 0) {
        float a = 0.0f, c = 0.0f;
        #pragma unroll
        for (int i = 0; i < 8; i++) { a += sr[i]; c += sm_[i]; }
        out[b]      = a + rb[0];
        out[B_ + b] = c + mb[0];
    }
}

// ---------------- driver ----------------
extern "C" void kernel_launch(void* const* d_in, const int* in_sizes, int n_in,
                              void* d_out, int out_size) {
    const int*   token_ids    = (const int*)  d_in[0];
    const int*   token_types  = (const int*)  d_in[1];
    const int*   amask        = (const int*)  d_in[2];
    const float* tok_emb      = (const float*)d_in[3];
    const float* type_emb     = (const float*)d_in[4];
    const float* norm1_w      = (const float*)d_in[5];
    const float* wq           = (const float*)d_in[6];
    const float* wk           = (const float*)d_in[7];
    const float* wv           = (const float*)d_in[8];
    const float* wo           = (const float*)d_in[9];
    const float* norm2_w      = (const float*)d_in[10];
    const float* ff_w1        = (const float*)d_in[11];
    const float* ff_w2        = (const float*)d_in[12];
    const float* final_norm_w = (const float*)d_in[13];
    const float* lm_w         = (const float*)d_in[14];
    const float* read_w       = (const float*)d_in[15];
    const float* read_b       = (const float*)d_in[16];
    const float* mort_w       = (const float*)d_in[17];
    const float* mort_b       = (const float*)d_in[18];
    float* out = (float*)d_out;

    float *x, *xn, *q, *k, *v, *at, *ff;
    __half *a16, *w16;
    cudaGetSymbolAddress((void**)&x,   g_x);
    cudaGetSymbolAddress((void**)&xn,  g_xn);
    cudaGetSymbolAddress((void**)&q,   g_q);
    cudaGetSymbolAddress((void**)&k,   g_k);
    cudaGetSymbolAddress((void**)&v,   g_v);
    cudaGetSymbolAddress((void**)&at,  g_at);
    cudaGetSymbolAddress((void**)&ff,  g_ff);
    cudaGetSymbolAddress((void**)&a16, g_a16);
    cudaGetSymbolAddress((void**)&w16, g_w16);

    cudaFuncSetAttribute(lm_f16, cudaFuncAttributeMaxDynamicSharedMemorySize, 49152);

    embed_k<<<MTOK * D_ / 256, 256>>>(token_ids, token_types, tok_emb, type_emb, x);

    dim3 gqkv(D_ / 64, MTOK / 128);
    dim3 gqkv3(3 * D_ / 64, MTOK / 128);
    dim3 gff1(FF_ / 64, MTOK / 128);
    for (int li = 0; li < NL_; li++) {
        rms_k<<<MTOK, 256>>>(x, norm1_w + li * D_, xn);
        gemm_qkv<<<gqkv3, 256>>>(xn, wq + (size_t)li * D_ * D_, wk + (size_t)li * D_ * D_,
                                 wv + (size_t)li * D_ * D_, q, k, v, D_);
        rope_k<<<MTOK * H_ * 32 / 256, 256>>>(q, k);
        attn_tc<<<dim3(L_ / 128, H_, B_), 128>>>(q, k, v, amask, at);
        gemm_f32<1><<<gqkv, 256>>>(at, wo + (size_t)li * D_ * D_, x, x, MTOK, D_, D_);
        rms_k<<<MTOK, 256>>>(x, norm2_w + li * D_, xn);
        gemm_f32<2><<<gff1, 256>>>(xn, ff_w1 + (size_t)li * FF_ * D_, nullptr, ff, MTOK, FF_, D_);
        gemm_f32<1><<<gqkv, 256>>>(ff, ff_w2 + (size_t)li * D_ * FF_, x, x, MTOK, D_, FF_);
    }
    rms_k<<<MTOK, 256>>>(x, final_norm_w, xn);
    cvt_f16_perm<<<MTOK * D_ / 256, 256>>>(xn, a16);
    cvt_f16_perm<<<V_ * D_ / 256, 256>>>(lm_w, w16);
    lm_f16<<<dim3(V_ / 128, MTOK / 128), 256, 49152>>>(a16, w16, out, MTOK, V_, D_);
    heads_k<<<B_, 256>>>(xn, read_w, read_b, mort_w, mort_b, out + (size_t)MTOK * V_);
}

// round 15
// speedup vs baseline: 3.5508x; 1.6976x over previous
#include <cuda_runtime.h>
#include <cuda_fp16.h>
#include <math.h>
#include <stdint.h>

#define B_   4
#define L_   2048
#define D_   256
#define H_   4
#define NL_  4
#define V_   32000
#define DH_  64
#define FF_  (4*D_)
#define MTOK (B_*L_)

// ---------------- scratch (allocation-free: __device__ globals) ----------------
__device__ float g_x [MTOK*D_];
__device__ float g_xn[MTOK*D_];
__device__ float g_q [MTOK*D_];
__device__ float g_k [MTOK*D_];
__device__ float g_v [MTOK*D_];
__device__ float g_ff[MTOK*FF_];                 // (fp32 ff no longer used; kept harmless)
__device__ __half g_xn16[MTOK*D_];               // rms out, fp16 pair-permuted
__device__ __half g_at16[MTOK*D_];               // attn out, fp16 pair-permuted
__device__ __half g_ff16[MTOK*FF_];              // silu out, fp16 pair-permuted
__device__ __half g_a16[MTOK*D_];                // LM activation
__device__ __half g_w16[(size_t)V_*D_];          // LM weight
__device__ __half g_wq16[NL_*D_*D_];
__device__ __half g_wk16[NL_*D_*D_];
__device__ __half g_wv16[NL_*D_*D_];
__device__ __half g_wo16[NL_*D_*D_];
__device__ __half g_wf1[NL_*FF_*D_];
__device__ __half g_wf2[NL_*D_*FF_];

// ---------------- helpers ----------------
__device__ __forceinline__ uint32_t smem_u32(const void* p) {
    uint32_t a;
    asm("{ .reg .u64 t; cvta.to.shared.u64 t, %1; cvt.u32.u64 %0, t; }" : "=r"(a) : "l"(p));
    return a;
}
#define CP_ASYNC16(dst_u32, src_ptr) \
    asm volatile("cp.async.cg.shared.global [%0], [%1], 16;" :: "r"(dst_u32), "l"(src_ptr))
#define CP_COMMIT() asm volatile("cp.async.commit_group;" ::: "memory")
#define CP_WAIT1()  asm volatile("cp.async.wait_group 1;" ::: "memory")

// pair-permutation within each 32-elem k-window:
// pair p (0..15) -> pos 4*(p&3)+(p>>2); element keeps its low bit.
__device__ __forceinline__ int kperm16(int kk) {   // kk in [0,32)
    int p = kk >> 1;
    int pos = 4 * (p & 3) + (p >> 2);
    return pos * 2 + (kk & 1);
}

// fp32 -> fp16 pair-permuted (bulk converter, used for weights + LM input)
__global__ void cvt_f16_perm(const float* __restrict__ x, __half* __restrict__ o) {
    int i = blockIdx.x * 256 + threadIdx.x;
    o[(i & ~31) | kperm16(i & 31)] = __float2half(x[i]);
}

// ---------------- embedding ----------------
__global__ void embed_k(const int* __restrict__ ids, const int* __restrict__ tys,
                        const float* __restrict__ tok_emb, const float* __restrict__ type_emb,
                        float* __restrict__ x) {
    int i = blockIdx.x * 256 + threadIdx.x;
    int t = i / D_, d = i - t * D_;
    x[i] = tok_emb[(size_t)ids[t] * D_ + d] + type_emb[tys[t] * D_ + d];
}

// ---------------- RMSNorm: fp32 out + fp16 pair-permuted out ----------------
__global__ void rms_k(const float* __restrict__ x, const float* __restrict__ w,
                      float* __restrict__ y, __half* __restrict__ y16) {
    int row = blockIdx.x;
    int d = threadIdx.x;
    float v = x[(size_t)row * D_ + d];
    float s = v * v;
    __shared__ float sh[8];
    #pragma unroll
    for (int o = 16; o; o >>= 1) s += __shfl_xor_sync(0xFFFFFFFFu, s, o);
    if ((threadIdx.x & 31) == 0) sh[threadIdx.x >> 5] = s;
    __syncthreads();
    if (threadIdx.x < 8) {
        float t = sh[threadIdx.x];
        #pragma unroll
        for (int o = 4; o; o >>= 1) t += __shfl_xor_sync(0xFFu, t, o);
        if (threadIdx.x == 0) sh[0] = t;
    }
    __syncthreads();
    float mean = sh[0] * (1.0f / D_);
    float r = rsqrtf(mean + 1.1920929e-07f);
    float o = v * r * w[d];
    y[(size_t)row * D_ + d] = o;
    y16[(size_t)row * D_ + (d & ~31) + kperm16(d & 31)] = __float2half(o);
}

// ---------------- RoPE ----------------
__global__ void rope_k(float* __restrict__ q, float* __restrict__ k) {
    int i = blockIdx.x * 256 + threadIdx.x;
    int j  = i & 31;
    int hh = (i >> 5) & (H_ - 1);
    int t  = i >> 7;
    int pos = t & (L_ - 1);
    float freq = expf(-logf(10000.0f) * (float)j * (1.0f / 32.0f));
    float ang = (float)pos * freq;
    float c = cosf(ang), s = sinf(ang);
    size_t base = (size_t)t * D_ + hh * DH_ + j;
    float q0 = q[base], q1 = q[base + 32];
    q[base]      = q0 * c - q1 * s;
    q[base + 32] = q1 * c + q0 * s;
    float k0 = k[base], k1 = k[base + 32];
    k[base]      = k0 * c - k1 * s;
    k[base + 32] = k1 * c + k0 * s;
}

// ---------------- tensor-core flash attention (R14-proven; fp16 permuted out) ----------------
#define MMA16(cc, a0, a1, a2, a3, bb0, bb1) \
    asm volatile("mma.sync.aligned.m16n8k16.row.col.f32.f16.f16.f32 " \
                 "{%0,%1,%2,%3}, {%4,%5,%6,%7}, {%8,%9}, {%0,%1,%2,%3};\n" \
                 : "+f"((cc)[0]), "+f"((cc)[1]), "+f"((cc)[2]), "+f"((cc)[3]) \
                 : "r"(a0), "r"(a1), "r"(a2), "r"(a3), "r"(bb0), "r"(bb1))

__device__ __forceinline__ unsigned f2h2(float a, float b) {
    __half2 h = __floats2half2_rn(a, b);
    return *(unsigned*)&h;
}

__global__ void __launch_bounds__(128) attn_tc(const float* __restrict__ q,
                                               const float* __restrict__ k,
                                               const float* __restrict__ v,
                                               const int* __restrict__ am,
                                               __half* __restrict__ out16) {
    const int h = blockIdx.y, b = blockIdx.z;
    const int tid = threadIdx.x, warp = tid >> 5, lane = tid & 31;
    const int g = lane >> 2, t4 = lane & 3;

    __shared__ __half Ks[64][72];
    __shared__ __half Vt[64][72];
    __shared__ int Ms[64];

    for (int hf = 0; hf < 2; hf++) {
        const int qt = (hf == 0) ? (int)(gridDim.x * 2 - 1 - blockIdx.x) : (int)blockIdx.x;
        const int rl0 = warp * 16 + g;
        const int rl1 = rl0 + 8;

        unsigned qa[4][4];
        {
            size_t qr0 = ((size_t)(b * L_) + qt * 64 + rl0) * D_ + h * DH_;
            size_t qr1 = qr0 + 8 * (size_t)D_;
            #pragma unroll
            for (int ks = 0; ks < 4; ks++) {
                int d0 = ks * 16 + t4 * 2;
                float2 x0 = *(const float2*)(q + qr0 + d0);
                float2 x1 = *(const float2*)(q + qr1 + d0);
                float2 x2 = *(const float2*)(q + qr0 + d0 + 8);
                float2 x3 = *(const float2*)(q + qr1 + d0 + 8);
                qa[ks][0] = f2h2(x0.x * 0.125f, x0.y * 0.125f);
                qa[ks][1] = f2h2(x1.x * 0.125f, x1.y * 0.125f);
                qa[ks][2] = f2h2(x2.x * 0.125f, x2.y * 0.125f);
                qa[ks][3] = f2h2(x3.x * 0.125f, x3.y * 0.125f);
            }
        }

        float m0 = -1e30f, m1 = -1e30f, l0 = 0.0f, l1 = 0.0f;
        float oa[8][4];
        #pragma unroll
        for (int dt = 0; dt < 8; dt++)
            #pragma unroll
            for (int f = 0; f < 4; f++) oa[dt][f] = 0.0f;

        for (int kt = 0; kt <= qt; kt++) {
            {
                int key = tid >> 1, dh = (tid & 1) * 32;
                const float* kg = k + ((size_t)(b * L_) + kt * 64 + key) * D_ + h * DH_ + dh;
                #pragma unroll
                for (int j = 0; j < 32; j += 4) {
                    float4 xv = *(const float4*)(kg + j);
                    *(__half2*)&Ks[key][dh + j]     = __floats2half2_rn(xv.x, xv.y);
                    *(__half2*)&Ks[key][dh + j + 2] = __floats2half2_rn(xv.z, xv.w);
                }
                int kp = tid & 31, dq = tid >> 5;
                const float* v0 = v + ((size_t)(b * L_) + kt * 64 + 2 * kp) * D_ + h * DH_ + dq * 16;
                const float* v1 = v0 + D_;
                #pragma unroll
                for (int j = 0; j < 16; j += 4) {
                    float4 a = *(const float4*)(v0 + j);
                    float4 c = *(const float4*)(v1 + j);
                    *(__half2*)&Vt[dq * 16 + j][2 * kp]     = __floats2half2_rn(a.x, c.x);
                    *(__half2*)&Vt[dq * 16 + j + 1][2 * kp] = __floats2half2_rn(a.y, c.y);
                    *(__half2*)&Vt[dq * 16 + j + 2][2 * kp] = __floats2half2_rn(a.z, c.z);
                    *(__half2*)&Vt[dq * 16 + j + 3][2 * kp] = __floats2half2_rn(a.w, c.w);
                }
                if (tid < 64) Ms[tid] = am[b * L_ + kt * 64 + tid];
            }
            __syncthreads();

            float sac[8][4];
            #pragma unroll
            for (int nt = 0; nt < 8; nt++)
                #pragma unroll
                for (int f = 0; f < 4; f++) sac[nt][f] = 0.0f;
            #pragma unroll
            for (int nt = 0; nt < 8; nt++) {
                #pragma unroll
                for (int ks = 0; ks < 4; ks++) {
                    unsigned bb0 = *(const unsigned*)&Ks[nt * 8 + g][ks * 16 + t4 * 2];
                    unsigned bb1 = *(const unsigned*)&Ks[nt * 8 + g][ks * 16 + t4 * 2 + 8];
                    MMA16(sac[nt], qa[ks][0], qa[ks][1], qa[ks][2], qa[ks][3], bb0, bb1);
                }
            }

            const bool last = (kt == qt);
            float mx0 = -1e30f, mx1 = -1e30f;
            #pragma unroll
            for (int nt = 0; nt < 8; nt++) {
                int c0 = nt * 8 + t4 * 2, c1 = c0 + 1;
                bool p0 = Ms[c0] != 0, p1 = Ms[c1] != 0;
                sac[nt][0] = (p0 && (!last || c0 <= rl0)) ? sac[nt][0] : -1e30f;
                sac[nt][1] = (p1 && (!last || c1 <= rl0)) ? sac[nt][1] : -1e30f;
                sac[nt][2] = (p0 && (!last || c0 <= rl1)) ? sac[nt][2] : -1e30f;
                sac[nt][3] = (p1 && (!last || c1 <= rl1)) ? sac[nt][3] : -1e30f;
                mx0 = fmaxf(mx0, fmaxf(sac[nt][0], sac[nt][1]));
                mx1 = fmaxf(mx1, fmaxf(sac[nt][2], sac[nt][3]));
            }
            mx0 = fmaxf(mx0, __shfl_xor_sync(0xFFFFFFFFu, mx0, 1));
            mx0 = fmaxf(mx0, __shfl_xor_sync(0xFFFFFFFFu, mx0, 2));
            mx1 = fmaxf(mx1, __shfl_xor_sync(0xFFFFFFFFu, mx1, 1));
            mx1 = fmaxf(mx1, __shfl_xor_sync(0xFFFFFFFFu, mx1, 2));
            float mn0 = fmaxf(m0, mx0), mn1 = fmaxf(m1, mx1);
            float sc0 = __expf(m0 - mn0), sc1 = __expf(m1 - mn1);
            m0 = mn0; m1 = mn1;

            float rs0 = 0.0f, rs1 = 0.0f;
            #pragma unroll
            for (int nt = 0; nt < 8; nt++) {
                sac[nt][0] = (sac[nt][0] > -1e29f) ? __expf(sac[nt][0] - m0) : 0.0f;
                sac[nt][1] = (sac[nt][1] > -1e29f) ? __expf(sac[nt][1] - m0) : 0.0f;
                sac[nt][2] = (sac[nt][2] > -1e29f) ? __expf(sac[nt][2] - m1) : 0.0f;
                sac[nt][3] = (sac[nt][3] > -1e29f) ? __expf(sac[nt][3] - m1) : 0.0f;
                rs0 += sac[nt][0] + sac[nt][1];
                rs1 += sac[nt][2] + sac[nt][3];
            }
            rs0 += __shfl_xor_sync(0xFFFFFFFFu, rs0, 1);
            rs0 += __shfl_xor_sync(0xFFFFFFFFu, rs0, 2);
            rs1 += __shfl_xor_sync(0xFFFFFFFFu, rs1, 1);
            rs1 += __shfl_xor_sync(0xFFFFFFFFu, rs1, 2);
            l0 = l0 * sc0 + rs0;
            l1 = l1 * sc1 + rs1;
            #pragma unroll
            for (int dt = 0; dt < 8; dt++) {
                oa[dt][0] *= sc0; oa[dt][1] *= sc0;
                oa[dt][2] *= sc1; oa[dt][3] *= sc1;
            }

            unsigned pa[4][4];
            #pragma unroll
            for (int kp = 0; kp < 4; kp++) {
                pa[kp][0] = f2h2(sac[2 * kp][0],     sac[2 * kp][1]);
                pa[kp][1] = f2h2(sac[2 * kp][2],     sac[2 * kp][3]);
                pa[kp][2] = f2h2(sac[2 * kp + 1][0], sac[2 * kp + 1][1]);
                pa[kp][3] = f2h2(sac[2 * kp + 1][2], sac[2 * kp + 1][3]);
            }
            #pragma unroll
            for (int dt = 0; dt < 8; dt++) {
                #pragma unroll
                for (int kp = 0; kp < 4; kp++) {
                    unsigned bb0 = *(const unsigned*)&Vt[dt * 8 + g][kp * 16 + t4 * 2];
                    unsigned bb1 = *(const unsigned*)&Vt[dt * 8 + g][kp * 16 + t4 * 2 + 8];
                    MMA16(oa[dt], pa[kp][0], pa[kp][1], pa[kp][2], pa[kp][3], bb0, bb1);
                }
            }
            __syncthreads();
        }

        float inv0 = (l0 > 0.0f) ? (1.0f / l0) : 0.0f;
        float inv1 = (l1 > 0.0f) ? (1.0f / l1) : 0.0f;
        size_t tok0 = (size_t)(b * L_) + qt * 64 + rl0;
        #pragma unroll
        for (int dt = 0; dt < 8; dt++) {
            int d = h * DH_ + dt * 8 + t4 * 2;                 // even pair
            int dp = (d & ~31) + kperm16(d & 31);              // permuted even pos
            *(__half2*)&out16[tok0 * D_ + dp] =
                __floats2half2_rn(oa[dt][0] * inv0, oa[dt][1] * inv0);
            *(__half2*)&out16[(tok0 + 8) * D_ + dp] =
                __floats2half2_rn(oa[dt][2] * inv1, oa[dt][3] * inv1);
        }
    }
}

// ---------------- fp16 tensor-core GEMM body (shared by all GEMMs) ----------------
// C[m,n] = sum_k A[m,k]*W[n,k]; A,W fp16 pair-permuted. fp32 acc.
// EPI 0: fp32 out.  EPI 1: fp32 out + residual R.  EPI 2: SiLU -> fp16 permuted out C16.
template <int EPI>
__device__ __forceinline__ void gemm16_body(const __half* __restrict__ A,
                                            const __half* __restrict__ W,
                                            const float* __restrict__ R,
                                            float* __restrict__ C,
                                            __half* __restrict__ C16,
                                            int N, int K, int bm, int bn,
                                            __half* sh16) {
    const uint32_t sb = smem_u32(sh16);
    const int tid = threadIdx.x;
    const int warp = tid >> 5, lane = tid & 31;
    const int wm = warp >> 2, wn = warp & 3;
    const int gid = lane >> 2, qid = lane & 3;
    const int nchunks = K >> 5;

    auto issue = [&](int ch, int s) {
        const uint32_t abase = sb + (uint32_t)(s * 8192) * 2u;
        const uint32_t wbase = abase + 4096u * 2u;
        #pragma unroll
        for (int t = 0; t < 2; t++) {
            int c2 = tid + t * 256;
            int row = c2 >> 2, seg = (c2 & 3) << 3;
            uint32_t dst = (uint32_t)(row * 32 + seg) * 2u;
            CP_ASYNC16(abase + dst, A + (size_t)(bm + row) * K + ch * 32 + seg);
            CP_ASYNC16(wbase + dst, W + (size_t)(bn + row) * K + ch * 32 + seg);
        }
    };

    float cacc[4][4][4];
    #pragma unroll
    for (int i = 0; i < 4; i++)
        #pragma unroll
        for (int j = 0; j < 4; j++)
            #pragma unroll
            for (int f = 0; f < 4; f++) cacc[i][j][f] = 0.0f;

    issue(0, 0); CP_COMMIT();
    issue(1, 1); CP_COMMIT();

    for (int ch = 0; ch < nchunks; ch++) {
        const int s = ch % 3;
        CP_WAIT1();
        __syncthreads();
        if (ch + 2 < nchunks) {
            issue(ch + 2, (ch + 2) % 3);
            CP_COMMIT();
        }
        const __half* Ab = sh16 + s * 8192;
        const __half* Wb = Ab + 4096;

        uint4 bb[4];
        #pragma unroll
        for (int nt = 0; nt < 4; nt++) {
            int rn = wn * 32 + nt * 8 + gid;
            bb[nt] = *(const uint4*)&Wb[rn * 32 + qid * 8];
        }
        #pragma unroll
        for (int mt = 0; mt < 4; mt++) {
            int r0 = wm * 64 + mt * 16 + gid;
            uint4 lo = *(const uint4*)&Ab[r0 * 32 + qid * 8];
            uint4 hi = *(const uint4*)&Ab[(r0 + 8) * 32 + qid * 8];
            #pragma unroll
            for (int nt = 0; nt < 4; nt++) {
                asm volatile(
                    "mma.sync.aligned.m16n8k16.row.col.f32.f16.f16.f32 "
                    "{%0,%1,%2,%3}, {%4,%5,%6,%7}, {%8,%9}, {%0,%1,%2,%3};\n"
                    : "+f"(cacc[mt][nt][0]), "+f"(cacc[mt][nt][1]),
                      "+f"(cacc[mt][nt][2]), "+f"(cacc[mt][nt][3])
                    : "r"(lo.x), "r"(hi.x), "r"(lo.y), "r"(hi.y),
                      "r"(bb[nt].x), "r"(bb[nt].y));
                asm volatile(
                    "mma.sync.aligned.m16n8k16.row.col.f32.f16.f16.f32 "
                    "{%0,%1,%2,%3}, {%4,%5,%6,%7}, {%8,%9}, {%0,%1,%2,%3};\n"
                    : "+f"(cacc[mt][nt][0]), "+f"(cacc[mt][nt][1]),
                      "+f"(cacc[mt][nt][2]), "+f"(cacc[mt][nt][3])
                    : "r"(lo.z), "r"(hi.z), "r"(lo.w), "r"(hi.w),
                      "r"(bb[nt].z), "r"(bb[nt].w));
            }
        }
    }

    #pragma unroll
    for (int mt = 0; mt < 4; mt++) {
        int row = bm + wm * 64 + mt * 16 + gid;
        #pragma unroll
        for (int nt = 0; nt < 4; nt++) {
            int col = bn + wn * 32 + nt * 8 + qid * 2;
            float c0 = cacc[mt][nt][0], c1 = cacc[mt][nt][1];
            float c2 = cacc[mt][nt][2], c3 = cacc[mt][nt][3];
            if (EPI == 2) {
                c0 = c0 / (1.0f + __expf(-c0));
                c1 = c1 / (1.0f + __expf(-c1));
                c2 = c2 / (1.0f + __expf(-c2));
                c3 = c3 / (1.0f + __expf(-c3));
                int dp = (col & ~31) + kperm16(col & 31);
                *(__half2*)&C16[(size_t)row * N + dp] = __floats2half2_rn(c0, c1);
                *(__half2*)&C16[(size_t)(row + 8) * N + dp] = __floats2half2_rn(c2, c3);
            } else {
                if (EPI == 1) {
                    float2 r0v = *(const float2*)(R + (size_t)row * N + col);
                    float2 r1v = *(const float2*)(R + (size_t)(row + 8) * N + col);
                    c0 += r0v.x; c1 += r0v.y; c2 += r1v.x; c3 += r1v.y;
                }
                *(float2*)(C + (size_t)row * N + col) = make_float2(c0, c1);
                *(float2*)(C + (size_t)(row + 8) * N + col) = make_float2(c2, c3);
            }
        }
    }
}

template <int EPI>
__global__ void __launch_bounds__(256, 2) gemm_f16k(const __half* __restrict__ A,
                                                    const __half* __restrict__ W,
                                                    const float* __restrict__ R,
                                                    float* __restrict__ C,
                                                    __half* __restrict__ C16,
                                                    int N, int K) {
    extern __shared__ __half sh16[];
    gemm16_body<EPI>(A, W, R, C, C16, N, K, blockIdx.y * 128, blockIdx.x * 128, sh16);
}

// fused QKV: blockIdx.x in [0,6): sel = bx>>1 picks matrix, bn = (bx&1)*128
__global__ void __launch_bounds__(256, 2) gemm_qkv16(const __half* __restrict__ A,
                                                     const __half* __restrict__ Wq,
                                                     const __half* __restrict__ Wk,
                                                     const __half* __restrict__ Wv,
                                                     float* __restrict__ q,
                                                     float* __restrict__ kk,
                                                     float* __restrict__ vv) {
    extern __shared__ __half sh16[];
    int sel = blockIdx.x >> 1;
    const __half* W = (sel == 0) ? Wq : (sel == 1) ? Wk : Wv;
    float*        C = (sel == 0) ? q  : (sel == 1) ? kk : vv;
    gemm16_body<0>(A, W, nullptr, C, nullptr, D_, D_,
                   blockIdx.y * 128, (blockIdx.x & 1) * 128, sh16);
}

// ---------------- LM head (R12-proven fp16 / fp32-acc) ----------------
__global__ void __launch_bounds__(256, 2) lm_f16(const __half* __restrict__ A,
                                                 const __half* __restrict__ W,
                                                 float* __restrict__ C,
                                                 int M, int N, int K) {
    extern __shared__ __half sh16[];
    gemm16_body<0>(A, W, nullptr, C, nullptr, N, K, blockIdx.y * 128, blockIdx.x * 128, sh16);
}

// ---------------- classifier heads on cls token (b, 0) ----------------
__global__ void heads_k(const float* __restrict__ xn,
                        const float* __restrict__ rw, const float* __restrict__ rb,
                        const float* __restrict__ mw, const float* __restrict__ mb,
                        float* __restrict__ out) {
    int b = blockIdx.x;
    int t = threadIdx.x;
    float xv = xn[((size_t)b * L_) * D_ + t];
    float pr = xv * rw[t];
    float pm = xv * mw[t];
    __shared__ float sr[8], sm_[8];
    #pragma unroll
    for (int o = 16; o; o >>= 1) {
        pr += __shfl_xor_sync(0xFFFFFFFFu, pr, o);
        pm += __shfl_xor_sync(0xFFFFFFFFu, pm, o);
    }
    if ((t & 31) == 0) { sr[t >> 5] = pr; sm_[t >> 5] = pm; }
    __syncthreads();
    if (t == 0) {
        float a = 0.0f, c = 0.0f;
        #pragma unroll
        for (int i = 0; i < 8; i++) { a += sr[i]; c += sm_[i]; }
        out[b]      = a + rb[0];
        out[B_ + b] = c + mb[0];
    }
}

// ---------------- driver ----------------
extern "C" void kernel_launch(void* const* d_in, const int* in_sizes, int n_in,
                              void* d_out, int out_size) {
    const int*   token_ids    = (const int*)  d_in[0];
    const int*   token_types  = (const int*)  d_in[1];
    const int*   amask        = (const int*)  d_in[2];
    const float* tok_emb      = (const float*)d_in[3];
    const float* type_emb     = (const float*)d_in[4];
    const float* norm1_w      = (const float*)d_in[5];
    const float* wq           = (const float*)d_in[6];
    const float* wk           = (const float*)d_in[7];
    const float* wv           = (const float*)d_in[8];
    const float* wo           = (const float*)d_in[9];
    const float* norm2_w      = (const float*)d_in[10];
    const float* ff_w1        = (const float*)d_in[11];
    const float* ff_w2        = (const float*)d_in[12];
    const float* final_norm_w = (const float*)d_in[13];
    const float* lm_w         = (const float*)d_in[14];
    const float* read_w       = (const float*)d_in[15];
    const float* read_b       = (const float*)d_in[16];
    const float* mort_w       = (const float*)d_in[17];
    const float* mort_b       = (const float*)d_in[18];
    float* out = (float*)d_out;

    float *x, *xn, *q, *k, *v;
    __half *xn16, *at16, *ff16, *a16, *w16;
    __half *wq16, *wk16, *wv16, *wo16, *wf1, *wf2;
    cudaGetSymbolAddress((void**)&x,    g_x);
    cudaGetSymbolAddress((void**)&xn,   g_xn);
    cudaGetSymbolAddress((void**)&q,    g_q);
    cudaGetSymbolAddress((void**)&k,    g_k);
    cudaGetSymbolAddress((void**)&v,    g_v);
    cudaGetSymbolAddress((void**)&xn16, g_xn16);
    cudaGetSymbolAddress((void**)&at16, g_at16);
    cudaGetSymbolAddress((void**)&ff16, g_ff16);
    cudaGetSymbolAddress((void**)&a16,  g_a16);
    cudaGetSymbolAddress((void**)&w16,  g_w16);
    cudaGetSymbolAddress((void**)&wq16, g_wq16);
    cudaGetSymbolAddress((void**)&wk16, g_wk16);
    cudaGetSymbolAddress((void**)&wv16, g_wv16);
    cudaGetSymbolAddress((void**)&wo16, g_wo16);
    cudaGetSymbolAddress((void**)&wf1,  g_wf1);
    cudaGetSymbolAddress((void**)&wf2,  g_wf2);

    cudaFuncSetAttribute(lm_f16,       cudaFuncAttributeMaxDynamicSharedMemorySize, 49152);
    cudaFuncSetAttribute(gemm_qkv16,   cudaFuncAttributeMaxDynamicSharedMemorySize, 49152);
    cudaFuncSetAttribute(gemm_f16k<1>, cudaFuncAttributeMaxDynamicSharedMemorySize, 49152);
    cudaFuncSetAttribute(gemm_f16k<2>, cudaFuncAttributeMaxDynamicSharedMemorySize, 49152);

    // weights -> fp16 pair-permuted (once per launch)
    cvt_f16_perm<<<NL_ * D_ * D_ / 256, 256>>>(wq, wq16);
    cvt_f16_perm<<<NL_ * D_ * D_ / 256, 256>>>(wk, wk16);
    cvt_f16_perm<<<NL_ * D_ * D_ / 256, 256>>>(wv, wv16);
    cvt_f16_perm<<<NL_ * D_ * D_ / 256, 256>>>(wo, wo16);
    cvt_f16_perm<<<NL_ * FF_ * D_ / 256, 256>>>(ff_w1, wf1);
    cvt_f16_perm<<<NL_ * D_ * FF_ / 256, 256>>>(ff_w2, wf2);

    embed_k<<<MTOK * D_ / 256, 256>>>(token_ids, token_types, tok_emb, type_emb, x);

    dim3 gmy(1, MTOK / 128);
    for (int li = 0; li < NL_; li++) {
        rms_k<<<MTOK, 256>>>(x, norm1_w + li * D_, xn, xn16);
        gemm_qkv16<<<dim3(6, MTOK / 128), 256, 49152>>>(
            xn16, wq16 + li * D_ * D_, wk16 + li * D_ * D_, wv16 + li * D_ * D_, q, k, v);
        rope_k<<<MTOK * H_ * 32 / 256, 256>>>(q, k);
        attn_tc<<<dim3(L_ / 128, H_, B_), 128>>>(q, k, v, amask, at16);
        gemm_f16k<1><<<dim3(2, MTOK / 128), 256, 49152>>>(
            at16, wo16 + li * D_ * D_, x, x, nullptr, D_, D_);
        rms_k<<<MTOK, 256>>>(x, norm2_w + li * D_, xn, xn16);
        gemm_f16k<2><<<dim3(8, MTOK / 128), 256, 49152>>>(
            xn16, wf1 + li * FF_ * D_, nullptr, nullptr, ff16, FF_, D_);
        gemm_f16k<1><<<dim3(2, MTOK / 128), 256, 49152>>>(
            ff16, wf2 + li * D_ * FF_, x, x, nullptr, D_, FF_);
    }
    rms_k<<<MTOK, 256>>>(x, final_norm_w, xn, a16);
    cvt_f16_perm<<<V_ * D_ / 256, 256>>>(lm_w, w16);
    lm_f16<<<dim3(V_ / 128, MTOK / 128), 256, 49152>>>(a16, w16, out, MTOK, V_, D_);
    heads_k<<<B_, 256>>>(xn, read_w, read_b, mort_w, mort_b, out + (size_t)MTOK * V_);
}

// round 16
// speedup vs baseline: 4.1515x; 1.1692x over previous
#include <cuda_runtime.h>
#include <cuda_fp16.h>
#include <math.h>
#include <stdint.h>

#define B_   4
#define L_   2048
#define D_   256
#define H_   4
#define NL_  4
#define V_   32000
#define DH_  64
#define FF_  (4*D_)
#define MTOK (B_*L_)

// ---------------- scratch (allocation-free: __device__ globals) ----------------
__device__ float g_x [MTOK*D_];
__device__ float g_xn[MTOK*D_];
__device__ float g_q [MTOK*D_];
__device__ float g_k [MTOK*D_];
__device__ float g_v [MTOK*D_];
__device__ __half g_q16[MTOK*D_];                // rope'd q, 0.125-scaled, [tok][dim]
__device__ __half g_k16[MTOK*D_];                // rope'd k, [tok][dim]
__device__ __half g_v16t[B_*H_*DH_*L_];          // v transposed: [(b*H+h)*DH+d][tok]
__device__ __half g_xn16[MTOK*D_];               // rms out, fp16 pair-permuted
__device__ __half g_at16[MTOK*D_];               // attn out, fp16 pair-permuted
__device__ __half g_ff16[MTOK*FF_];              // silu out, fp16 pair-permuted
__device__ __half g_a16[MTOK*D_];                // LM activation
__device__ __half g_w16[(size_t)V_*D_];          // LM weight
__device__ __half g_wq16[NL_*D_*D_];
__device__ __half g_wk16[NL_*D_*D_];
__device__ __half g_wv16[NL_*D_*D_];
__device__ __half g_wo16[NL_*D_*D_];
__device__ __half g_wf1[NL_*FF_*D_];
__device__ __half g_wf2[NL_*D_*FF_];

// ---------------- helpers ----------------
__device__ __forceinline__ uint32_t smem_u32(const void* p) {
    uint32_t a;
    asm("{ .reg .u64 t; cvta.to.shared.u64 t, %1; cvt.u32.u64 %0, t; }" : "=r"(a) : "l"(p));
    return a;
}
#define CP_ASYNC16(dst_u32, src_ptr) \
    asm volatile("cp.async.cg.shared.global [%0], [%1], 16;" :: "r"(dst_u32), "l"(src_ptr))
#define CP_COMMIT() asm volatile("cp.async.commit_group;" ::: "memory")
#define CP_WAIT1()  asm volatile("cp.async.wait_group 1;" ::: "memory")

__device__ __forceinline__ int kperm16(int kk) {   // kk in [0,32)
    int p = kk >> 1;
    int pos = 4 * (p & 3) + (p >> 2);
    return pos * 2 + (kk & 1);
}

__global__ void cvt_f16_perm(const float* __restrict__ x, __half* __restrict__ o) {
    int i = blockIdx.x * 256 + threadIdx.x;
    o[(i & ~31) | kperm16(i & 31)] = __float2half(x[i]);
}

// ---------------- embedding ----------------
__global__ void embed_k(const int* __restrict__ ids, const int* __restrict__ tys,
                        const float* __restrict__ tok_emb, const float* __restrict__ type_emb,
                        float* __restrict__ x) {
    int i = blockIdx.x * 256 + threadIdx.x;
    int t = i / D_, d = i - t * D_;
    x[i] = tok_emb[(size_t)ids[t] * D_ + d] + type_emb[tys[t] * D_ + d];
}

// ---------------- RMSNorm: fp32 out + fp16 pair-permuted out ----------------
__global__ void rms_k(const float* __restrict__ x, const float* __restrict__ w,
                      float* __restrict__ y, __half* __restrict__ y16) {
    int row = blockIdx.x;
    int d = threadIdx.x;
    float v = x[(size_t)row * D_ + d];
    float s = v * v;
    __shared__ float sh[8];
    #pragma unroll
    for (int o = 16; o; o >>= 1) s += __shfl_xor_sync(0xFFFFFFFFu, s, o);
    if ((threadIdx.x & 31) == 0) sh[threadIdx.x >> 5] = s;
    __syncthreads();
    if (threadIdx.x < 8) {
        float t = sh[threadIdx.x];
        #pragma unroll
        for (int o = 4; o; o >>= 1) t += __shfl_xor_sync(0xFFu, t, o);
        if (threadIdx.x == 0) sh[0] = t;
    }
    __syncthreads();
    float mean = sh[0] * (1.0f / D_);
    float r = rsqrtf(mean + 1.1920929e-07f);
    float o = v * r * w[d];
    y[(size_t)row * D_ + d] = o;
    y16[(size_t)row * D_ + (d & ~31) + kperm16(d & 31)] = __float2half(o);
}

// ---------------- RoPE -> fp16 (q pre-scaled by 0.125) ----------------
__global__ void rope_qk_k(const float* __restrict__ q, const float* __restrict__ k,
                          __half* __restrict__ q16, __half* __restrict__ k16) {
    int i = blockIdx.x * 256 + threadIdx.x;          // over MTOK*H*32
    int j  = i & 31;
    int hh = (i >> 5) & (H_ - 1);
    int t  = i >> 7;
    int pos = t & (L_ - 1);
    float freq = expf(-logf(10000.0f) * (float)j * (1.0f / 32.0f));
    float ang = (float)pos * freq;
    float c = cosf(ang), s = sinf(ang);
    size_t base = (size_t)t * D_ + hh * DH_ + j;
    float q0 = q[base], q1 = q[base + 32];
    q16[base]      = __float2half((q0 * c - q1 * s) * 0.125f);
    q16[base + 32] = __float2half((q1 * c + q0 * s) * 0.125f);
    float k0 = k[base], k1 = k[base + 32];
    k16[base]      = __float2half(k0 * c - k1 * s);
    k16[base + 32] = __float2half(k1 * c + k0 * s);
}

// ---------------- V transpose-convert: v[tok][dim] -> v16t[(b,h,d)][tok] ----------------
__global__ void vt_k(const float* __restrict__ v, __half* __restrict__ vt) {
    __shared__ float tile[32][33];
    int t0 = blockIdx.x * 32;                         // token base
    int d0 = blockIdx.y * 32;                         // dim base (0..255)
    int tx = threadIdx.x & 31, ty = threadIdx.x >> 5; // 32 x 8
    #pragma unroll
    for (int u = 0; u < 4; u++)
        tile[ty + u * 8][tx] = v[(size_t)(t0 + ty + u * 8) * D_ + d0 + tx];
    __syncthreads();
    int b = t0 / L_;
    int h = d0 / DH_;
    int dl = d0 % DH_;
    #pragma unroll
    for (int u = 0; u < 4; u++) {
        int d = dl + ty + u * 8;
        vt[((size_t)(b * H_ + h) * DH_ + d) * L_ + (t0 % L_) + tx] =
            __float2half(tile[tx][ty + u * 8]);
    }
}

// ---------------- tensor-core flash attention (fp16 inputs; fp16 permuted out) ----------------
#define MMA16(cc, a0, a1, a2, a3, bb0, bb1) \
    asm volatile("mma.sync.aligned.m16n8k16.row.col.f32.f16.f16.f32 " \
                 "{%0,%1,%2,%3}, {%4,%5,%6,%7}, {%8,%9}, {%0,%1,%2,%3};\n" \
                 : "+f"((cc)[0]), "+f"((cc)[1]), "+f"((cc)[2]), "+f"((cc)[3]) \
                 : "r"(a0), "r"(a1), "r"(a2), "r"(a3), "r"(bb0), "r"(bb1))

__device__ __forceinline__ unsigned f2h2(float a, float b) {
    __half2 h = __floats2half2_rn(a, b);
    return *(unsigned*)&h;
}

__global__ void __launch_bounds__(128) attn_tc(const __half* __restrict__ q16,
                                               const __half* __restrict__ k16,
                                               const __half* __restrict__ v16t,
                                               const int* __restrict__ am,
                                               __half* __restrict__ out16) {
    const int h = blockIdx.y, b = blockIdx.z;
    const int tid = threadIdx.x, warp = tid >> 5, lane = tid & 31;
    const int g = lane >> 2, t4 = lane & 3;

    __shared__ __half Ks[64][72];
    __shared__ __half Vt[64][72];
    __shared__ int Ms[64];

    for (int hf = 0; hf < 2; hf++) {
        const int qt = (hf == 0) ? (int)(gridDim.x * 2 - 1 - blockIdx.x) : (int)blockIdx.x;
        const int rl0 = warp * 16 + g;
        const int rl1 = rl0 + 8;

        unsigned qa[4][4];
        {
            size_t qr0 = ((size_t)(b * L_) + qt * 64 + rl0) * D_ + h * DH_;
            size_t qr1 = qr0 + 8 * (size_t)D_;
            #pragma unroll
            for (int ks = 0; ks < 4; ks++) {
                int d0 = ks * 16 + t4 * 2;
                qa[ks][0] = *(const unsigned*)(q16 + qr0 + d0);
                qa[ks][1] = *(const unsigned*)(q16 + qr1 + d0);
                qa[ks][2] = *(const unsigned*)(q16 + qr0 + d0 + 8);
                qa[ks][3] = *(const unsigned*)(q16 + qr1 + d0 + 8);
            }
        }

        float m0 = -1e30f, m1 = -1e30f, l0 = 0.0f, l1 = 0.0f;
        float oa[8][4];
        #pragma unroll
        for (int dt = 0; dt < 8; dt++)
            #pragma unroll
            for (int f = 0; f < 4; f++) oa[dt][f] = 0.0f;

        for (int kt = 0; kt <= qt; kt++) {
            {   // K tile: 2 threads per row, 4 uint4 each
                int key = tid >> 1, hseg = (tid & 1) * 32;
                const uint4* src = (const uint4*)(k16 + ((size_t)(b * L_) + kt * 64 + key) * D_
                                                  + h * DH_ + hseg);
                uint4* dst = (uint4*)&Ks[key][hseg];
                #pragma unroll
                for (int u = 0; u < 4; u++) dst[u] = src[u];
                // Vt tile: 2 threads per dim-row
                int d = tid >> 1;
                const uint4* vs = (const uint4*)(v16t + ((size_t)(b * H_ + h) * DH_ + d) * L_
                                                 + kt * 64 + hseg);
                uint4* vd = (uint4*)&Vt[d][hseg];
                #pragma unroll
                for (int u = 0; u < 4; u++) vd[u] = vs[u];
                if (tid < 64) Ms[tid] = am[b * L_ + kt * 64 + tid];
            }
            __syncthreads();

            float sac[8][4];
            #pragma unroll
            for (int nt = 0; nt < 8; nt++)
                #pragma unroll
                for (int f = 0; f < 4; f++) sac[nt][f] = 0.0f;
            #pragma unroll
            for (int nt = 0; nt < 8; nt++) {
                #pragma unroll
                for (int ks = 0; ks < 4; ks++) {
                    unsigned bb0 = *(const unsigned*)&Ks[nt * 8 + g][ks * 16 + t4 * 2];
                    unsigned bb1 = *(const unsigned*)&Ks[nt * 8 + g][ks * 16 + t4 * 2 + 8];
                    MMA16(sac[nt], qa[ks][0], qa[ks][1], qa[ks][2], qa[ks][3], bb0, bb1);
                }
            }

            const bool last = (kt == qt);
            float mx0 = -1e30f, mx1 = -1e30f;
            #pragma unroll
            for (int nt = 0; nt < 8; nt++) {
                int c0 = nt * 8 + t4 * 2, c1 = c0 + 1;
                bool p0 = Ms[c0] != 0, p1 = Ms[c1] != 0;
                sac[nt][0] = (p0 && (!last || c0 <= rl0)) ? sac[nt][0] : -1e30f;
                sac[nt][1] = (p1 && (!last || c1 <= rl0)) ? sac[nt][1] : -1e30f;
                sac[nt][2] = (p0 && (!last || c0 <= rl1)) ? sac[nt][2] : -1e30f;
                sac[nt][3] = (p1 && (!last || c1 <= rl1)) ? sac[nt][3] : -1e30f;
                mx0 = fmaxf(mx0, fmaxf(sac[nt][0], sac[nt][1]));
                mx1 = fmaxf(mx1, fmaxf(sac[nt][2], sac[nt][3]));
            }
            mx0 = fmaxf(mx0, __shfl_xor_sync(0xFFFFFFFFu, mx0, 1));
            mx0 = fmaxf(mx0, __shfl_xor_sync(0xFFFFFFFFu, mx0, 2));
            mx1 = fmaxf(mx1, __shfl_xor_sync(0xFFFFFFFFu, mx1, 1));
            mx1 = fmaxf(mx1, __shfl_xor_sync(0xFFFFFFFFu, mx1, 2));
            float mn0 = fmaxf(m0, mx0), mn1 = fmaxf(m1, mx1);
            float sc0 = __expf(m0 - mn0), sc1 = __expf(m1 - mn1);
            m0 = mn0; m1 = mn1;

            float rs0 = 0.0f, rs1 = 0.0f;
            #pragma unroll
            for (int nt = 0; nt < 8; nt++) {
                sac[nt][0] = (sac[nt][0] > -1e29f) ? __expf(sac[nt][0] - m0) : 0.0f;
                sac[nt][1] = (sac[nt][1] > -1e29f) ? __expf(sac[nt][1] - m0) : 0.0f;
                sac[nt][2] = (sac[nt][2] > -1e29f) ? __expf(sac[nt][2] - m1) : 0.0f;
                sac[nt][3] = (sac[nt][3] > -1e29f) ? __expf(sac[nt][3] - m1) : 0.0f;
                rs0 += sac[nt][0] + sac[nt][1];
                rs1 += sac[nt][2] + sac[nt][3];
            }
            rs0 += __shfl_xor_sync(0xFFFFFFFFu, rs0, 1);
            rs0 += __shfl_xor_sync(0xFFFFFFFFu, rs0, 2);
            rs1 += __shfl_xor_sync(0xFFFFFFFFu, rs1, 1);
            rs1 += __shfl_xor_sync(0xFFFFFFFFu, rs1, 2);
            l0 = l0 * sc0 + rs0;
            l1 = l1 * sc1 + rs1;
            #pragma unroll
            for (int dt = 0; dt < 8; dt++) {
                oa[dt][0] *= sc0; oa[dt][1] *= sc0;
                oa[dt][2] *= sc1; oa[dt][3] *= sc1;
            }

            unsigned pa[4][4];
            #pragma unroll
            for (int kp = 0; kp < 4; kp++) {
                pa[kp][0] = f2h2(sac[2 * kp][0],     sac[2 * kp][1]);
                pa[kp][1] = f2h2(sac[2 * kp][2],     sac[2 * kp][3]);
                pa[kp][2] = f2h2(sac[2 * kp + 1][0], sac[2 * kp + 1][1]);
                pa[kp][3] = f2h2(sac[2 * kp + 1][2], sac[2 * kp + 1][3]);
            }
            #pragma unroll
            for (int dt = 0; dt < 8; dt++) {
                #pragma unroll
                for (int kp = 0; kp < 4; kp++) {
                    unsigned bb0 = *(const unsigned*)&Vt[dt * 8 + g][kp * 16 + t4 * 2];
                    unsigned bb1 = *(const unsigned*)&Vt[dt * 8 + g][kp * 16 + t4 * 2 + 8];
                    MMA16(oa[dt], pa[kp][0], pa[kp][1], pa[kp][2], pa[kp][3], bb0, bb1);
                }
            }
            __syncthreads();
        }

        float inv0 = (l0 > 0.0f) ? (1.0f / l0) : 0.0f;
        float inv1 = (l1 > 0.0f) ? (1.0f / l1) : 0.0f;
        size_t tok0 = (size_t)(b * L_) + qt * 64 + rl0;
        #pragma unroll
        for (int dt = 0; dt < 8; dt++) {
            int d = h * DH_ + dt * 8 + t4 * 2;
            int dp = (d & ~31) + kperm16(d & 31);
            *(__half2*)&out16[tok0 * D_ + dp] =
                __floats2half2_rn(oa[dt][0] * inv0, oa[dt][1] * inv0);
            *(__half2*)&out16[(tok0 + 8) * D_ + dp] =
                __floats2half2_rn(oa[dt][2] * inv1, oa[dt][3] * inv1);
        }
    }
}

// ---------------- fp16 tensor-core GEMM body (shared by all GEMMs) ----------------
template <int EPI>
__device__ __forceinline__ void gemm16_body(const __half* __restrict__ A,
                                            const __half* __restrict__ W,
                                            const float* __restrict__ R,
                                            float* __restrict__ C,
                                            __half* __restrict__ C16,
                                            int N, int K, int bm, int bn,
                                            __half* sh16) {
    const uint32_t sb = smem_u32(sh16);
    const int tid = threadIdx.x;
    const int warp = tid >> 5, lane = tid & 31;
    const int wm = warp >> 2, wn = warp & 3;
    const int gid = lane >> 2, qid = lane & 3;
    const int nchunks = K >> 5;

    auto issue = [&](int ch, int s) {
        const uint32_t abase = sb + (uint32_t)(s * 8192) * 2u;
        const uint32_t wbase = abase + 4096u * 2u;
        #pragma unroll
        for (int t = 0; t < 2; t++) {
            int c2 = tid + t * 256;
            int row = c2 >> 2, seg = (c2 & 3) << 3;
            uint32_t dst = (uint32_t)(row * 32 + seg) * 2u;
            CP_ASYNC16(abase + dst, A + (size_t)(bm + row) * K + ch * 32 + seg);
            CP_ASYNC16(wbase + dst, W + (size_t)(bn + row) * K + ch * 32 + seg);
        }
    };

    float cacc[4][4][4];
    #pragma unroll
    for (int i = 0; i < 4; i++)
        #pragma unroll
        for (int j = 0; j < 4; j++)
            #pragma unroll
            for (int f = 0; f < 4; f++) cacc[i][j][f] = 0.0f;

    issue(0, 0); CP_COMMIT();
    issue(1, 1); CP_COMMIT();

    for (int ch = 0; ch < nchunks; ch++) {
        const int s = ch % 3;
        CP_WAIT1();
        __syncthreads();
        if (ch + 2 < nchunks) {
            issue(ch + 2, (ch + 2) % 3);
            CP_COMMIT();
        }
        const __half* Ab = sh16 + s * 8192;
        const __half* Wb = Ab + 4096;

        uint4 bb[4];
        #pragma unroll
        for (int nt = 0; nt < 4; nt++) {
            int rn = wn * 32 + nt * 8 + gid;
            bb[nt] = *(const uint4*)&Wb[rn * 32 + qid * 8];
        }
        #pragma unroll
        for (int mt = 0; mt < 4; mt++) {
            int r0 = wm * 64 + mt * 16 + gid;
            uint4 lo = *(const uint4*)&Ab[r0 * 32 + qid * 8];
            uint4 hi = *(const uint4*)&Ab[(r0 + 8) * 32 + qid * 8];
            #pragma unroll
            for (int nt = 0; nt < 4; nt++) {
                asm volatile(
                    "mma.sync.aligned.m16n8k16.row.col.f32.f16.f16.f32 "
                    "{%0,%1,%2,%3}, {%4,%5,%6,%7}, {%8,%9}, {%0,%1,%2,%3};\n"
                    : "+f"(cacc[mt][nt][0]), "+f"(cacc[mt][nt][1]),
                      "+f"(cacc[mt][nt][2]), "+f"(cacc[mt][nt][3])
                    : "r"(lo.x), "r"(hi.x), "r"(lo.y), "r"(hi.y),
                      "r"(bb[nt].x), "r"(bb[nt].y));
                asm volatile(
                    "mma.sync.aligned.m16n8k16.row.col.f32.f16.f16.f32 "
                    "{%0,%1,%2,%3}, {%4,%5,%6,%7}, {%8,%9}, {%0,%1,%2,%3};\n"
                    : "+f"(cacc[mt][nt][0]), "+f"(cacc[mt][nt][1]),
                      "+f"(cacc[mt][nt][2]), "+f"(cacc[mt][nt][3])
                    : "r"(lo.z), "r"(hi.z), "r"(lo.w), "r"(hi.w),
                      "r"(bb[nt].z), "r"(bb[nt].w));
            }
        }
    }

    #pragma unroll
    for (int mt = 0; mt < 4; mt++) {
        int row = bm + wm * 64 + mt * 16 + gid;
        #pragma unroll
        for (int nt = 0; nt < 4; nt++) {
            int col = bn + wn * 32 + nt * 8 + qid * 2;
            float c0 = cacc[mt][nt][0], c1 = cacc[mt][nt][1];
            float c2 = cacc[mt][nt][2], c3 = cacc[mt][nt][3];
            if (EPI == 2) {
                c0 = c0 / (1.0f + __expf(-c0));
                c1 = c1 / (1.0f + __expf(-c1));
                c2 = c2 / (1.0f + __expf(-c2));
                c3 = c3 / (1.0f + __expf(-c3));
                int dp = (col & ~31) + kperm16(col & 31);
                *(__half2*)&C16[(size_t)row * N + dp] = __floats2half2_rn(c0, c1);
                *(__half2*)&C16[(size_t)(row + 8) * N + dp] = __floats2half2_rn(c2, c3);
            } else {
                if (EPI == 1) {
                    float2 r0v = *(const float2*)(R + (size_t)row * N + col);
                    float2 r1v = *(const float2*)(R + (size_t)(row + 8) * N + col);
                    c0 += r0v.x; c1 += r0v.y; c2 += r1v.x; c3 += r1v.y;
                }
                *(float2*)(C + (size_t)row * N + col) = make_float2(c0, c1);
                *(float2*)(C + (size_t)(row + 8) * N + col) = make_float2(c2, c3);
            }
        }
    }
}

template <int EPI>
__global__ void __launch_bounds__(256, 2) gemm_f16k(const __half* __restrict__ A,
                                                    const __half* __restrict__ W,
                                                    const float* __restrict__ R,
                                                    float* __restrict__ C,
                                                    __half* __restrict__ C16,
                                                    int N, int K) {
    extern __shared__ __half sh16[];
    gemm16_body<EPI>(A, W, R, C, C16, N, K, blockIdx.y * 128, blockIdx.x * 128, sh16);
}

__global__ void __launch_bounds__(256, 2) gemm_qkv16(const __half* __restrict__ A,
                                                     const __half* __restrict__ Wq,
                                                     const __half* __restrict__ Wk,
                                                     const __half* __restrict__ Wv,
                                                     float* __restrict__ q,
                                                     float* __restrict__ kk,
                                                     float* __restrict__ vv) {
    extern __shared__ __half sh16[];
    int sel = blockIdx.x >> 1;
    const __half* W = (sel == 0) ? Wq : (sel == 1) ? Wk : Wv;
    float*        C = (sel == 0) ? q  : (sel == 1) ? kk : vv;
    gemm16_body<0>(A, W, nullptr, C, nullptr, D_, D_,
                   blockIdx.y * 128, (blockIdx.x & 1) * 128, sh16);
}

__global__ void __launch_bounds__(256, 2) lm_f16(const __half* __restrict__ A,
                                                 const __half* __restrict__ W,
                                                 float* __restrict__ C,
                                                 int M, int N, int K) {
    extern __shared__ __half sh16[];
    gemm16_body<0>(A, W, nullptr, C, nullptr, N, K, blockIdx.y * 128, blockIdx.x * 128, sh16);
}

// ---------------- classifier heads on cls token (b, 0) ----------------
__global__ void heads_k(const float* __restrict__ xn,
                        const float* __restrict__ rw, const float* __restrict__ rb,
                        const float* __restrict__ mw, const float* __restrict__ mb,
                        float* __restrict__ out) {
    int b = blockIdx.x;
    int t = threadIdx.x;
    float xv = xn[((size_t)b * L_) * D_ + t];
    float pr = xv * rw[t];
    float pm = xv * mw[t];
    __shared__ float sr[8], sm_[8];
    #pragma unroll
    for (int o = 16; o; o >>= 1) {
        pr += __shfl_xor_sync(0xFFFFFFFFu, pr, o);
        pm += __shfl_xor_sync(0xFFFFFFFFu, pm, o);
    }
    if ((t & 31) == 0) { sr[t >> 5] = pr; sm_[t >> 5] = pm; }
    __syncthreads();
    if (t == 0) {
        float a = 0.0f, c = 0.0f;
        #pragma unroll
        for (int i = 0; i < 8; i++) { a += sr[i]; c += sm_[i]; }
        out[b]      = a + rb[0];
        out[B_ + b] = c + mb[0];
    }
}

// ---------------- driver ----------------
extern "C" void kernel_launch(void* const* d_in, const int* in_sizes, int n_in,
                              void* d_out, int out_size) {
    const int*   token_ids    = (const int*)  d_in[0];
    const int*   token_types  = (const int*)  d_in[1];
    const int*   amask        = (const int*)  d_in[2];
    const float* tok_emb      = (const float*)d_in[3];
    const float* type_emb     = (const float*)d_in[4];
    const float* norm1_w      = (const float*)d_in[5];
    const float* wq           = (const float*)d_in[6];
    const float* wk           = (const float*)d_in[7];
    const float* wv           = (const float*)d_in[8];
    const float* wo           = (const float*)d_in[9];
    const float* norm2_w      = (const float*)d_in[10];
    const float* ff_w1        = (const float*)d_in[11];
    const float* ff_w2        = (const float*)d_in[12];
    const float* final_norm_w = (const float*)d_in[13];
    const float* lm_w         = (const float*)d_in[14];
    const float* read_w       = (const float*)d_in[15];
    const float* read_b       = (const float*)d_in[16];
    const float* mort_w       = (const float*)d_in[17];
    const float* mort_b       = (const float*)d_in[18];
    float* out = (float*)d_out;

    float *x, *xn, *q, *k, *v;
    __half *q16, *k16, *v16t, *xn16, *at16, *ff16, *a16, *w16;
    __half *wq16, *wk16, *wv16, *wo16, *wf1, *wf2;
    cudaGetSymbolAddress((void**)&x,    g_x);
    cudaGetSymbolAddress((void**)&xn,   g_xn);
    cudaGetSymbolAddress((void**)&q,    g_q);
    cudaGetSymbolAddress((void**)&k,    g_k);
    cudaGetSymbolAddress((void**)&v,    g_v);
    cudaGetSymbolAddress((void**)&q16,  g_q16);
    cudaGetSymbolAddress((void**)&k16,  g_k16);
    cudaGetSymbolAddress((void**)&v16t, g_v16t);
    cudaGetSymbolAddress((void**)&xn16, g_xn16);
    cudaGetSymbolAddress((void**)&at16, g_at16);
    cudaGetSymbolAddress((void**)&ff16, g_ff16);
    cudaGetSymbolAddress((void**)&a16,  g_a16);
    cudaGetSymbolAddress((void**)&w16,  g_w16);
    cudaGetSymbolAddress((void**)&wq16, g_wq16);
    cudaGetSymbolAddress((void**)&wk16, g_wk16);
    cudaGetSymbolAddress((void**)&wv16, g_wv16);
    cudaGetSymbolAddress((void**)&wo16, g_wo16);
    cudaGetSymbolAddress((void**)&wf1,  g_wf1);
    cudaGetSymbolAddress((void**)&wf2,  g_wf2);

    cudaFuncSetAttribute(lm_f16,       cudaFuncAttributeMaxDynamicSharedMemorySize, 49152);
    cudaFuncSetAttribute(gemm_qkv16,   cudaFuncAttributeMaxDynamicSharedMemorySize, 49152);
    cudaFuncSetAttribute(gemm_f16k<1>, cudaFuncAttributeMaxDynamicSharedMemorySize, 49152);
    cudaFuncSetAttribute(gemm_f16k<2>, cudaFuncAttributeMaxDynamicSharedMemorySize, 49152);

    cvt_f16_perm<<<NL_ * D_ * D_ / 256, 256>>>(wq, wq16);
    cvt_f16_perm<<<NL_ * D_ * D_ / 256, 256>>>(wk, wk16);
    cvt_f16_perm<<<NL_ * D_ * D_ / 256, 256>>>(wv, wv16);
    cvt_f16_perm<<<NL_ * D_ * D_ / 256, 256>>>(wo, wo16);
    cvt_f16_perm<<<NL_ * FF_ * D_ / 256, 256>>>(ff_w1, wf1);
    cvt_f16_perm<<<NL_ * D_ * FF_ / 256, 256>>>(ff_w2, wf2);

    embed_k<<<MTOK * D_ / 256, 256>>>(token_ids, token_types, tok_emb, type_emb, x);

    for (int li = 0; li < NL_; li++) {
        rms_k<<<MTOK, 256>>>(x, norm1_w + li * D_, xn, xn16);
        gemm_qkv16<<<dim3(6, MTOK / 128), 256, 49152>>>(
            xn16, wq16 + li * D_ * D_, wk16 + li * D_ * D_, wv16 + li * D_ * D_, q, k, v);
        rope_qk_k<<<MTOK * H_ * 32 / 256, 256>>>(q, k, q16, k16);
        vt_k<<<dim3(MTOK / 32, D_ / 32), 256>>>(v, v16t);
        attn_tc<<<dim3(L_ / 128, H_, B_), 128>>>(q16, k16, v16t, amask, at16);
        gemm_f16k<1><<<dim3(2, MTOK / 128), 256, 49152>>>(
            at16, wo16 + li * D_ * D_, x, x, nullptr, D_, D_);
        rms_k<<<MTOK, 256>>>(x, norm2_w + li * D_, xn, xn16);
        gemm_f16k<2><<<dim3(8, MTOK / 128), 256, 49152>>>(
            xn16, wf1 + li * FF_ * D_, nullptr, nullptr, ff16, FF_, D_);
        gemm_f16k<1><<<dim3(2, MTOK / 128), 256, 49152>>>(
            ff16, wf2 + li * D_ * FF_, x, x, nullptr, D_, FF_);
    }
    rms_k<<<MTOK, 256>>>(x, final_norm_w, xn, a16);
    cvt_f16_perm<<<V_ * D_ / 256, 256>>>(lm_w, w16);
    lm_f16<<<dim3(V_ / 128, MTOK / 128), 256, 49152>>>(a16, w16, out, MTOK, V_, D_);
    heads_k<<<B_, 256>>>(xn, read_w, read_b, mort_w, mort_b, out + (size_t)MTOK * V_);
}